// round 13
// baseline (speedup 1.0000x reference)
#include <cuda_runtime.h>
#include <cuda_bf16.h>
#include <math.h>
#include <stdint.h>

#define BB 32
#define NN 520
#define DEPOTN 20
#define CUSTN 500
#define EE 128
#define HH 8
#define DKK 16
#define FFHH 512
#define NLL 6
#define MM 520
#define LL 40
#define KRT 288

typedef __nv_bfloat16 bf16;

// ---------------- fp32 scratch ----------------
__device__ __align__(16) float g_x   [BB*NN*EE];     // final encoder output only
__device__ __align__(16) float g_y   [BB*NN*EE];
__device__ __align__(16) float g_flag [BB*MM];
__device__ __align__(16) float g_sn   [BB*MM*NN];

// ---------------- bf16 hi/lo scratch ----------------
__device__ __align__(16) bf16 g_xh[BB*NN*EE],      g_xl[BB*NN*EE];
__device__ __align__(16) bf16 g_x1h[BB*NN*EE],     g_x1l[BB*NN*EE];
__device__ __align__(16) bf16 g_mhh[BB*NN*EE],     g_mhl[BB*NN*EE];
__device__ __align__(16) bf16 g_qkvh[BB*NN*384],   g_qkvl[BB*NN*384];
__device__ __align__(16) bf16 g_kvdh[BB*NN*256],   g_kvdl[BB*NN*256];
__device__ __align__(16) bf16 g_qlch[BB*MM*EE],    g_qlcl[BB*MM*EE];
__device__ __align__(16) bf16 g_qrth[BB*MM*EE],    g_qrtl[BB*MM*EE];
__device__ __align__(16) bf16 g_ffhh[BB*NN*FFHH],  g_ffhl[BB*NN*FFHH];
__device__ __align__(16) bf16 g_attnh[BB*MM*EE],   g_attnl[BB*MM*EE];
__device__ __align__(16) bf16 g_scoreh[BB*MM*EE],  g_scorel[BB*MM*EE];
__device__ __align__(16) bf16 g_catlh[BB*MM*256],  g_catll[BB*MM*256];
__device__ __align__(16) bf16 g_catrh[BB*MM*KRT],  g_catrl[BB*MM*KRT];
__device__ __align__(16) bf16 g_wqkvh[NLL*384*EE], g_wqkvl[NLL*384*EE];
__device__ __align__(16) bf16 g_wch[NLL*EE*EE],    g_wcl[NLL*EE*EE];
__device__ __align__(16) bf16 g_f1h[NLL*FFHH*EE],  g_f1l[NLL*FFHH*EE];
__device__ __align__(16) bf16 g_f2h[NLL*EE*FFHH],  g_f2l[NLL*EE*FFHH];
__device__ __align__(16) bf16 g_wkvh[256*EE],      g_wkvl[256*EE];
__device__ __align__(16) bf16 g_wqlh[EE*256],      g_wqll[EE*256];
__device__ __align__(16) bf16 g_wpah[EE*KRT],      g_wpal[EE*KRT];
__device__ __align__(16) bf16 g_wdch[EE*EE],       g_wdcl[EE*EE];

__device__ __forceinline__ void split1(float x, bf16* h, bf16* l)
{
    bf16 hv = __float2bfloat16(x);
    *h = hv;
    *l = __float2bfloat16(x - __bfloat162float(hv));
}

__device__ __forceinline__ void cvtpk(float x0, float x1, uint32_t& h, uint32_t& l)
{
    bf16 h0 = __float2bfloat16(x0), h1 = __float2bfloat16(x1);
    float l0 = x0 - __bfloat162float(h0), l1 = x1 - __bfloat162float(h1);
    h = ((uint32_t)__bfloat16_as_ushort(h1) << 16) | __bfloat16_as_ushort(h0);
    bf16 g0 = __float2bfloat16(l0), g1 = __float2bfloat16(l1);
    l = ((uint32_t)__bfloat16_as_ushort(g1) << 16) | __bfloat16_as_ushort(g0);
}

__device__ __forceinline__ float2 rec2(uint32_t h, uint32_t l)
{
    float2 r;
    r.x = __bfloat162float(__ushort_as_bfloat16((unsigned short)(h & 0xffff)))
        + __bfloat162float(__ushort_as_bfloat16((unsigned short)(l & 0xffff)));
    r.y = __bfloat162float(__ushort_as_bfloat16((unsigned short)(h >> 16)))
        + __bfloat162float(__ushort_as_bfloat16((unsigned short)(l >> 16)));
    return r;
}

// ---------------- generic fp32 -> hi/lo ----------------
__global__ void cvt_split(const float* __restrict__ s, bf16* __restrict__ h,
                          bf16* __restrict__ l, int n)
{
    int i = blockIdx.x * blockDim.x + threadIdx.x;
    if (i < n) split1(s[i], h + i, l + i);
}

// ---------------- embedding (hi/lo only) ----------------
__global__ void embed_kernel(const float* __restrict__ dep, const float* __restrict__ cus,
                             const float* __restrict__ Wd, const float* __restrict__ bd,
                             const float* __restrict__ Wc, const float* __restrict__ bc)
{
    int idx = blockIdx.x * blockDim.x + threadIdx.x;
    if (idx >= BB*NN*EE) return;
    int e = idx % EE;
    int n = (idx / EE) % NN;
    int b = idx / (EE*NN);
    float acc;
    if (n < DEPOTN) {
        const float* f = dep + ((long)b*DEPOTN + n) * 4;
        acc = bd[e];
        #pragma unroll
        for (int j = 0; j < 4; j++) acc += f[j] * Wd[e*4 + j];
    } else {
        const float* f = cus + ((long)b*CUSTN + (n - DEPOTN)) * 3;
        acc = bc[e];
        #pragma unroll
        for (int j = 0; j < 3; j++) acc += f[j] * Wc[e*3 + j];
    }
    split1(acc, g_xh + idx, g_xl + idx);
}

// ---------------- weight packing ----------------
__global__ void pack_w(const float* __restrict__ Wq, const float* __restrict__ Wk,
                       const float* __restrict__ Wv, const float* __restrict__ dWk,
                       const float* __restrict__ dWv)
{
    int idx = blockIdx.x * blockDim.x + threadIdx.x;
    const int tot1 = NLL*384*EE;
    if (idx < tot1) {
        int col = idx % EE;
        int row = (idx / EE) % 384;
        int l   = idx / (EE*384);
        float v;
        if (row < 128)      v = Wq[((long)l*EE + row)*EE + col];
        else if (row < 256) v = Wk[((long)l*EE + row-128)*EE + col];
        else                v = Wv[((long)l*EE + row-256)*EE + col];
        split1(v, g_wqkvh + idx, g_wqkvl + idx);
    } else {
        int j = idx - tot1;
        if (j < 256*EE) {
            int col = j % EE;
            int row = j / EE;
            float v = (row < 128) ? dWk[row*EE + col] : dWv[(row-128)*EE + col];
            split1(v, g_wkvh + j, g_wkvl + j);
        }
    }
}

__global__ void padw_kernel(const float* __restrict__ Wr)
{
    int idx = blockIdx.x * blockDim.x + threadIdx.x;
    if (idx >= EE*KRT) return;
    int rr = idx / KRT, cc = idx % KRT;
    float v = (cc < 257) ? Wr[rr*257 + cc] : 0.f;
    split1(v, g_wpah + idx, g_wpal + idx);
}

// ---------------- MMA primitives ----------------
#define LDM4(r0,r1,r2,r3,addr) \
    asm volatile("ldmatrix.sync.aligned.m8n8.x4.shared.b16 {%0,%1,%2,%3},[%4];" \
                 : "=r"(r0),"=r"(r1),"=r"(r2),"=r"(r3) : "r"(addr))
#define LDM2(r0,r1,addr) \
    asm volatile("ldmatrix.sync.aligned.m8n8.x2.shared.b16 {%0,%1},[%2];" \
                 : "=r"(r0),"=r"(r1) : "r"(addr))
#define MMA16816(c,a,b) \
    asm volatile("mma.sync.aligned.m16n8k16.row.col.f32.bf16.bf16.f32 " \
                 "{%0,%1,%2,%3},{%4,%5,%6,%7},{%8,%9},{%0,%1,%2,%3};" \
                 : "+f"((c)[0]),"+f"((c)[1]),"+f"((c)[2]),"+f"((c)[3]) \
                 : "r"((a)[0]),"r"((a)[1]),"r"((a)[2]),"r"((a)[3]), "r"((b)[0]),"r"((b)[1]))

// ---------------- TC GEMM: pass-major, hi/lo resid ----------------
#define MAT 10240
#define STAGE 40960

__global__ __launch_bounds__(256, 2)
void gemm_tc2(const bf16* __restrict__ Ahi, const bf16* __restrict__ Alo,
              const bf16* __restrict__ Bhi, const bf16* __restrict__ Blo,
              const float* __restrict__ bias,
              const bf16* __restrict__ Rh, const bf16* __restrict__ Rl,
              float* __restrict__ C, bf16* __restrict__ Chi, bf16* __restrict__ Clo,
              int R, int K, int Cout, long sA, long sB, long sC, int relu)
{
    int bz = blockIdx.z;
    Ahi += (long)bz*sA; Alo += (long)bz*sA;
    Bhi += (long)bz*sB; Blo += (long)bz*sB;
    if (C)     C   += (long)bz*sC;
    if (Chi) { Chi += (long)bz*sC; Clo += (long)bz*sC; }
    if (Rh)  { Rh  += (long)bz*sC; Rl  += (long)bz*sC; }

    extern __shared__ bf16 smb[];
    uint32_t sb = (uint32_t)__cvta_generic_to_shared(smb);

    int tid = threadIdx.x, lane = tid & 31, warp = tid >> 5;
    int wm = warp >> 2, wn = warp & 3;
    int rowBase = blockIdx.x * 128, colBase = blockIdx.y * 128;

    float c[4][4][4];
    #pragma unroll
    for (int i = 0; i < 4; i++)
        #pragma unroll
        for (int j = 0; j < 4; j++)
            { c[i][j][0]=0.f; c[i][j][1]=0.f; c[i][j][2]=0.f; c[i][j][3]=0.f; }

    const bf16* bases[4] = { Ahi, Alo, Bhi, Blo };
    int nk = K >> 5;

    #define FILL(st, kt) do { \
        int k0 = (kt) << 5; \
        _Pragma("unroll") \
        for (int t = 0; t < 8; t++) { \
            int o = tid + t*256; \
            int m = o >> 9, r = (o >> 2) & 127, seg = o & 3; \
            int gr = ((m < 2) ? rowBase : colBase) + r; \
            int lim = (m < 2) ? R : Cout; \
            long grc = (gr < lim) ? gr : 0; \
            const bf16* src = bases[m] + grc*K + k0 + seg*8; \
            uint32_t dst = sb + (st)*STAGE + m*MAT + r*80 + seg*16; \
            int nbytes = (gr < lim) ? 16 : 0; \
            asm volatile("cp.async.ca.shared.global [%0],[%1],16,%2;" \
                         :: "r"(dst), "l"(src), "r"(nbytes)); \
        } \
        asm volatile("cp.async.commit_group;"); \
    } while (0)

    FILL(0, 0);

    int ar = lane & 15, ak = (lane >> 4);
    int br = lane & 7,  bk = (lane >> 3) & 1;

    for (int kt = 0; kt < nk; kt++) {
        int st = kt & 1;
        if (kt + 1 < nk) {
            FILL(st ^ 1, kt + 1);
            asm volatile("cp.async.wait_group 1;");
        } else {
            asm volatile("cp.async.wait_group 0;");
        }
        __syncthreads();

        uint32_t aOff = sb + st*STAGE;
        uint32_t bOff = aOff + 2*MAT;
        #pragma unroll
        for (int ks = 0; ks < 2; ks++) {
            uint32_t Ah[4][4], Al[4][4];
            #pragma unroll
            for (int i = 0; i < 4; i++) {
                uint32_t ad = aOff + (uint32_t)((wm*64 + i*16 + ar)*80 + ak*16 + ks*32);
                LDM4(Ah[i][0], Ah[i][1], Ah[i][2], Ah[i][3], ad);
                LDM4(Al[i][0], Al[i][1], Al[i][2], Al[i][3], ad + MAT);
            }
            #pragma unroll
            for (int jp = 0; jp < 2; jp++) {
                uint32_t Bh[2][2], Bl[2][2];
                #pragma unroll
                for (int jj = 0; jj < 2; jj++) {
                    int j = jp*2 + jj;
                    uint32_t bd = bOff + (uint32_t)((wn*32 + j*8 + br)*80 + bk*16 + ks*32);
                    LDM2(Bh[jj][0], Bh[jj][1], bd);
                    LDM2(Bl[jj][0], Bl[jj][1], bd + MAT);
                }
                #pragma unroll
                for (int jj = 0; jj < 2; jj++)
                    #pragma unroll
                    for (int i = 0; i < 4; i++)
                        MMA16816(c[i][jp*2+jj], Ah[i], Bh[jj]);
                #pragma unroll
                for (int jj = 0; jj < 2; jj++)
                    #pragma unroll
                    for (int i = 0; i < 4; i++)
                        MMA16816(c[i][jp*2+jj], Ah[i], Bl[jj]);
                #pragma unroll
                for (int jj = 0; jj < 2; jj++)
                    #pragma unroll
                    for (int i = 0; i < 4; i++)
                        MMA16816(c[i][jp*2+jj], Al[i], Bh[jj]);
            }
        }
        __syncthreads();
    }

    int gid = lane >> 2, tig = lane & 3;
    #pragma unroll
    for (int i = 0; i < 4; i++) {
        int rbase = rowBase + wm*64 + i*16 + gid;
        #pragma unroll
        for (int j = 0; j < 4; j++) {
            int c0 = colBase + wn*32 + j*8 + tig*2;
            if (c0 >= Cout) continue;
            #pragma unroll
            for (int hh = 0; hh < 2; hh++) {
                int row = rbase + hh*8;
                if (row >= R) continue;
                float v0 = c[i][j][2*hh], v1 = c[i][j][2*hh+1];
                if (bias)  { v0 += bias[c0]; v1 += bias[c0+1]; }
                if (Rh) {
                    uint32_t rh = *(const uint32_t*)(Rh + (long)row*Cout + c0);
                    uint32_t rl = *(const uint32_t*)(Rl + (long)row*Cout + c0);
                    float2 rv = rec2(rh, rl);
                    v0 += rv.x; v1 += rv.y;
                }
                if (relu) { v0 = fmaxf(v0, 0.f); v1 = fmaxf(v1, 0.f); }
                if (C) *(float2*)(C + (long)row*Cout + c0) = make_float2(v0, v1);
                if (Chi) {
                    uint32_t hp, lp;
                    cvtpk(v0, v1, hp, lp);
                    *(uint32_t*)(Chi + (long)row*Cout + c0) = hp;
                    *(uint32_t*)(Clo + (long)row*Cout + c0) = lp;
                }
            }
        }
    }
}

// ---------------- attention: hi/lo in, one block per (h,b), q-tiles looped ----------------
#define KPAD 576
#define KLO_B  27648
#define VHI_B  55296
#define VLO_B  18688
#define QHI_B  92672
#define QLO_B  6144
#define ATTN2_SMEM 104960
#define NQT 5

__global__ __launch_bounds__(256)
void attn_mma(const bf16* __restrict__ Qhg, const bf16* __restrict__ Qlg,
              const bf16* __restrict__ Q2hg, const bf16* __restrict__ Q2lg,
              const float* __restrict__ flagv, int ldq,
              const bf16* __restrict__ Khg, const bf16* __restrict__ Klg, int ldk,
              const bf16* __restrict__ Vhg, const bf16* __restrict__ Vlg, int ldv,
              const float* __restrict__ mask,
              bf16* __restrict__ Oh, bf16* __restrict__ Ol)
{
    int h = blockIdx.x, b = blockIdx.y;
    extern __shared__ bf16 sm2[];
    uint32_t sb = (uint32_t)__cvta_generic_to_shared(sm2);
    int tid = threadIdx.x;

    const int KHI_E = 0, KLO_E = 13824, VHI_E = 27648, VLO_E = 36992;
    const int QHI_E = 46336, QLO_E = 49408;

    const bf16* Khb = Khg + (long)b*NN*ldk + h*DKK;
    const bf16* Klb = Klg + (long)b*NN*ldk + h*DKK;
    const bf16* Vhb = Vhg + (long)b*NN*ldv + h*DKK;
    const bf16* Vlb = Vlg + (long)b*NN*ldv + h*DKK;
    const bf16 Z = __float2bfloat16(0.f);
    for (int i = tid; i < KPAD*DKK; i += 256) {
        int key = i >> 4, d = i & 15;
        bool in = key < NN;
        long o = (long)key*ldk + d;
        long ov = (long)key*ldv + d;
        sm2[KHI_E + key*24 + d]  = in ? Khb[o]  : Z;
        sm2[KLO_E + key*24 + d]  = in ? Klb[o]  : Z;
        sm2[VHI_E + d*584 + key] = in ? Vhb[ov] : Z;
        sm2[VLO_E + d*584 + key] = in ? Vlb[ov] : Z;
    }

    const bf16* Qhb = Qhg + (long)b*NN*ldq + h*DKK;
    const bf16* Qlb = Qlg + (long)b*NN*ldq + h*DKK;
    const bf16* Q2hb = Q2hg ? (Q2hg + (long)b*NN*ldq + h*DKK) : (const bf16*)0;
    const bf16* Q2lb = Q2hg ? (Q2lg + (long)b*NN*ldq + h*DKK) : (const bf16*)0;

    int warp = tid >> 5, lane = tid & 31;
    int g = lane >> 2;
    int ar = lane & 15, ak = lane >> 4;
    int br = lane & 7,  bk = (lane >> 3) & 1;
    const unsigned FULL = 0xffffffffu;

    #pragma unroll 1
    for (int qt = 0; qt < NQT; qt++) {
        int qb = qt * 128;
        __syncthreads();
        for (int i = tid; i < 128*DKK; i += 256) {
            int row = i >> 4, d = i & 15;
            int q = qb + row;
            if (q < NN) {
                long o = (long)q*ldq + d;
                if (Q2hb) {
                    float f = flagv[(long)b*MM + q];
                    float qv = f*(__bfloat162float(Qhb[o]) + __bfloat162float(Qlb[o]))
                             + (1.f - f)*(__bfloat162float(Q2hb[o]) + __bfloat162float(Q2lb[o]));
                    bf16 qh = __float2bfloat16(qv);
                    sm2[QHI_E + row*24 + d] = qh;
                    sm2[QLO_E + row*24 + d] = __float2bfloat16(qv - __bfloat162float(qh));
                } else {
                    sm2[QHI_E + row*24 + d] = Qhb[o];
                    sm2[QLO_E + row*24 + d] = Qlb[o];
                }
            } else {
                sm2[QHI_E + row*24 + d] = Z;
                sm2[QLO_E + row*24 + d] = Z;
            }
        }
        __syncthreads();

        if ((qb + warp*16) >= NN) continue;

        uint32_t Qh[4], Ql[4];
        {
            uint32_t qa = sb + QHI_B + (uint32_t)((warp*16 + ar)*48 + ak*16);
            LDM4(Qh[0], Qh[1], Qh[2], Qh[3], qa);
            LDM4(Ql[0], Ql[1], Ql[2], Ql[3], qa + QLO_B);
        }

        float oA[2][4], oB[2][4], oC[2][4];
        #pragma unroll
        for (int n = 0; n < 2; n++)
            #pragma unroll
            for (int q = 0; q < 4; q++) { oA[n][q]=0.f; oB[n][q]=0.f; oC[n][q]=0.f; }
        float mrow[2] = { -1e30f, -1e30f };
        float lrow[2] = { 0.f, 0.f };

        int qr0 = qb + warp*16 + g;
        int qm0 = (qr0 < NN) ? qr0 : NN-1;
        int qm1 = (qr0+8 < NN) ? qr0+8 : NN-1;
        const float* mk0 = mask ? (mask + ((long)(b*MM + qm0))*NN) : (const float*)0;
        const float* mk1 = mask ? (mask + ((long)(b*MM + qm1))*NN) : (const float*)0;

        #pragma unroll 1
        for (int c = 0; c < 9; c++) {
            float s[8][4];
            uint32_t Bh[8][2], Bl[8][2];
            #pragma unroll
            for (int t = 0; t < 8; t++) {
                uint32_t ka = sb + (uint32_t)((c*64 + t*8 + br)*48 + bk*16);
                LDM2(Bh[t][0], Bh[t][1], ka);
                LDM2(Bl[t][0], Bl[t][1], ka + KLO_B);
                s[t][0]=0.f; s[t][1]=0.f; s[t][2]=0.f; s[t][3]=0.f;
            }
            #pragma unroll
            for (int t = 0; t < 8; t++) MMA16816(s[t], Qh, Bh[t]);
            #pragma unroll
            for (int t = 0; t < 8; t++) MMA16816(s[t], Qh, Bl[t]);
            #pragma unroll
            for (int t = 0; t < 8; t++) MMA16816(s[t], Ql, Bh[t]);

            float mx0 = -1e30f, mx1 = -1e30f;
            #pragma unroll
            for (int t = 0; t < 8; t++) {
                if (c < 8 || t == 0) {
                    s[t][0]*=0.25f; s[t][1]*=0.25f; s[t][2]*=0.25f; s[t][3]*=0.25f;
                    if (mask) {
                        int j = c*64 + t*8 + (lane&3)*2;
                        float2 m0 = *(const float2*)(mk0 + j);
                        float2 m1 = *(const float2*)(mk1 + j);
                        s[t][0]+=m0.x; s[t][1]+=m0.y; s[t][2]+=m1.x; s[t][3]+=m1.y;
                    }
                } else {
                    s[t][0]=-1e30f; s[t][1]=-1e30f; s[t][2]=-1e30f; s[t][3]=-1e30f;
                }
                mx0 = fmaxf(mx0, fmaxf(s[t][0], s[t][1]));
                mx1 = fmaxf(mx1, fmaxf(s[t][2], s[t][3]));
            }
            mx0 = fmaxf(mx0, __shfl_xor_sync(FULL, mx0, 1));
            mx0 = fmaxf(mx0, __shfl_xor_sync(FULL, mx0, 2));
            mx1 = fmaxf(mx1, __shfl_xor_sync(FULL, mx1, 1));
            mx1 = fmaxf(mx1, __shfl_xor_sync(FULL, mx1, 2));
            float mn0 = fmaxf(mrow[0], mx0), mn1 = fmaxf(mrow[1], mx1);
            float f0 = __expf(mrow[0] - mn0), f1 = __expf(mrow[1] - mn1);
            mrow[0] = mn0; mrow[1] = mn1;
            float rs0 = 0.f, rs1 = 0.f;
            #pragma unroll
            for (int t = 0; t < 8; t++) {
                s[t][0] = __expf(s[t][0] - mn0);
                s[t][1] = __expf(s[t][1] - mn0);
                s[t][2] = __expf(s[t][2] - mn1);
                s[t][3] = __expf(s[t][3] - mn1);
                rs0 += s[t][0] + s[t][1];
                rs1 += s[t][2] + s[t][3];
            }
            rs0 += __shfl_xor_sync(FULL, rs0, 1); rs0 += __shfl_xor_sync(FULL, rs0, 2);
            rs1 += __shfl_xor_sync(FULL, rs1, 1); rs1 += __shfl_xor_sync(FULL, rs1, 2);
            lrow[0] = lrow[0]*f0 + rs0;
            lrow[1] = lrow[1]*f1 + rs1;
            #pragma unroll
            for (int n = 0; n < 2; n++) {
                oA[n][0]*=f0; oA[n][1]*=f0; oA[n][2]*=f1; oA[n][3]*=f1;
                oB[n][0]*=f0; oB[n][1]*=f0; oB[n][2]*=f1; oB[n][3]*=f1;
                oC[n][0]*=f0; oC[n][1]*=f0; oC[n][2]*=f1; oC[n][3]*=f1;
            }
            #pragma unroll
            for (int ss = 0; ss < 4; ss++) {
                uint32_t pah[4], pal[4];
                cvtpk(s[2*ss][0],   s[2*ss][1],   pah[0], pal[0]);
                cvtpk(s[2*ss][2],   s[2*ss][3],   pah[1], pal[1]);
                cvtpk(s[2*ss+1][0], s[2*ss+1][1], pah[2], pal[2]);
                cvtpk(s[2*ss+1][2], s[2*ss+1][3], pah[3], pal[3]);
                #pragma unroll
                for (int n = 0; n < 2; n++) {
                    uint32_t va = sb + VHI_B +
                        (uint32_t)((n*8 + br)*1168 + (c*64 + ss*16)*2 + bk*16);
                    uint32_t vh[2], vl[2];
                    LDM2(vh[0], vh[1], va);
                    LDM2(vl[0], vl[1], va + VLO_B);
                    MMA16816(oA[n], pah, vh);
                    MMA16816(oB[n], pah, vl);
                    MMA16816(oC[n], pal, vh);
                }
            }
        }

        float i0 = 1.f / lrow[0], i1 = 1.f / lrow[1];
        #pragma unroll
        for (int n = 0; n < 2; n++) {
            int d = h*DKK + n*8 + (lane&3)*2;
            if (qr0 < NN) {
                uint32_t hp, lp;
                cvtpk((oA[n][0]+oB[n][0]+oC[n][0])*i0,
                      (oA[n][1]+oB[n][1]+oC[n][1])*i0, hp, lp);
                long off = ((long)(b*NN + qr0))*EE + d;
                *(uint32_t*)(Oh + off) = hp;
                *(uint32_t*)(Ol + off) = lp;
            }
            if (qr0 + 8 < NN) {
                uint32_t hp, lp;
                cvtpk((oA[n][2]+oB[n][2]+oC[n][2])*i1,
                      (oA[n][3]+oB[n][3]+oC[n][3])*i1, hp, lp);
                long off = ((long)(b*NN + qr0 + 8))*EE + d;
                *(uint32_t*)(Oh + off) = hp;
                *(uint32_t*)(Ol + off) = lp;
            }
        }
    }
}

// ---------------- fused instance norm: stats + apply in one kernel ----------------
// grid (BB, 4); block owns (batch b, 32-channel group); writes hi/lo (+fp32 if Xo)
__global__ __launch_bounds__(512)
void inorm_fused(const float* __restrict__ Y, const float* __restrict__ gg,
                 const float* __restrict__ bt, float* __restrict__ Xo,
                 bf16* __restrict__ Xh, bf16* __restrict__ Xl)
{
    int b = blockIdx.x, eg = blockIdx.y;
    int tid = threadIdx.x;
    int el = tid & 31, nch = tid >> 5;     // 16 node chunks
    int e = eg*32 + el;
    float s1 = 0.f, s2 = 0.f;
    for (int n = nch; n < NN; n += 16) {
        float v = Y[((long)(b*NN + n))*EE + e];
        s1 += v; s2 += v*v;
    }
    __shared__ float sh1[512], sh2[512];
    __shared__ float smean[32], sistd[32];
    sh1[tid] = s1; sh2[tid] = s2;
    __syncthreads();
    #pragma unroll
    for (int off = 256; off >= 32; off >>= 1) {
        if (tid < off) { sh1[tid] += sh1[tid+off]; sh2[tid] += sh2[tid+off]; }
        __syncthreads();
    }
    if (tid < 32) {
        float mean = sh1[tid] / (float)NN;
        float var  = sh2[tid] / (float)NN - mean*mean;
        smean[tid] = mean;
        sistd[tid] = rsqrtf(var + 1e-5f);
    }
    __syncthreads();
    float mean = smean[el], istd = sistd[el];
    float gv = gg[e], bv = bt[e];
    for (int n = nch; n < NN; n += 16) {
        long idx = ((long)(b*NN + n))*EE + e;
        float v = (Y[idx] - mean) * istd * gv + bv;
        if (Xo) Xo[idx] = v;
        split1(v, Xh + idx, Xl + idx);
    }
}

// ---------------- decoder helpers ----------------
__global__ void build_cat(const float* __restrict__ loadv, const int* __restrict__ cur,
                          const int* __restrict__ subn, const int* __restrict__ subl,
                          const int* __restrict__ sel, const float* __restrict__ encmean)
{
    int r = blockIdx.x;
    int b = r / MM;
    int e = threadIdx.x;
    int c = cur[r];
    float le = g_x[((long)(b*NN + c))*EE + e];

    int len = subl[r];
    const int* nodes = subn + (long)r*LL;
    float ssum = 0.f; int cnt = 0;
    for (int l = 0; l < LL; l++) {
        int nd = nodes[l];
        if (l < len && nd >= DEPOTN) {
            ssum += g_x[((long)(b*NN + nd))*EE + e];
            cnt++;
        }
    }
    float cntf = (cnt > 0) ? (float)cnt : 1.f;
    float smean = ssum / cntf;

    long bl = (long)r*256, br = (long)r*KRT;
    split1(le,    g_catlh + bl + e,       g_catll + bl + e);
    split1(smean, g_catlh + bl + 128 + e, g_catll + bl + 128 + e);
    split1(le,    g_catrh + br + e,       g_catrl + br + e);
    split1(encmean[e], g_catrh + br + 128 + e, g_catrl + br + 128 + e);
    if (e == 0) split1(loadv[r], g_catrh + br + 256, g_catrl + br + 256);
    if (e >= 1 && e < 32) { g_catrh[br + 256 + e] = __float2bfloat16(0.f);
                            g_catrl[br + 256 + e] = __float2bfloat16(0.f); }
    if (e == 0) {
        int s2 = sel[(long)r*4 + 2];
        g_flag[r] = (s2 >= DEPOTN && c < DEPOTN) ? 1.f : 0.f;
    }
}

// ---------------- final tanh-clip + mask + softmax ----------------
__global__ void final_kernel(const float* __restrict__ mask, float* __restrict__ out)
{
    int r = blockIdx.x;
    int tid = threadIdx.x;
    __shared__ float buf[NN];
    __shared__ float red[256];
    const float* sn = g_sn + (long)r*NN;
    const float* mk = mask + (long)r*NN;
    const float invs = 0.08838834764831845f;

    float lm = -1e30f;
    for (int j = tid; j < NN; j += 256) {
        float v = 10.f * tanhf(sn[j] * invs) + mk[j];
        buf[j] = v;
        lm = fmaxf(lm, v);
    }
    red[tid] = lm; __syncthreads();
    for (int off = 128; off > 0; off >>= 1) {
        if (tid < off) red[tid] = fmaxf(red[tid], red[tid+off]);
        __syncthreads();
    }
    float mx = red[0]; __syncthreads();

    float ls = 0.f;
    for (int j = tid; j < NN; j += 256) {
        float e0 = __expf(buf[j] - mx);
        buf[j] = e0; ls += e0;
    }
    red[tid] = ls; __syncthreads();
    for (int off = 128; off > 0; off >>= 1) {
        if (tid < off) red[tid] += red[tid+off];
        __syncthreads();
    }
    float inv = 1.f / red[0];
    for (int j = tid; j < NN; j += 256)
        out[(long)r*NN + j] = buf[j] * inv;
}

// ---------------- host ----------------
#define GEMM_SMEM 81920

static void launch_tc(const bf16* Ah, const bf16* Al, const bf16* Bh, const bf16* Bl,
                      const float* bias, const bf16* Rh, const bf16* Rl,
                      float* C, bf16* Ch, bf16* Cl,
                      int R, int K, int Cout, int batch,
                      long sA, long sB, long sC, int relu)
{
    dim3 grid((R + 127) / 128, (Cout + 127) / 128, batch);
    gemm_tc2<<<grid, 256, GEMM_SMEM>>>(Ah, Al, Bh, Bl, bias, Rh, Rl, C, Ch, Cl,
                                       R, K, Cout, sA, sB, sC, relu);
}

#define SYM(p, s) cudaGetSymbolAddress((void**)&p, s)

extern "C" void kernel_launch(void* const* d_in, const int* in_sizes, int n_in,
                              void* d_out, int out_size)
{
    const float* depot  = (const float*)d_in[0];
    const float* cust   = (const float*)d_in[1];
    const float* mask   = (const float*)d_in[2];
    const float* loadv  = (const float*)d_in[3];
    const int*   cur    = (const int*)d_in[4];
    const int*   subn   = (const int*)d_in[5];
    const int*   subl   = (const int*)d_in[6];
    const int*   sel    = (const int*)d_in[7];
    const float* edW    = (const float*)d_in[8];
    const float* edb    = (const float*)d_in[9];
    const float* ecW    = (const float*)d_in[10];
    const float* ecb    = (const float*)d_in[11];
    const float* Wq     = (const float*)d_in[12];
    const float* Wk     = (const float*)d_in[13];
    const float* Wv     = (const float*)d_in[14];
    const float* Wc     = (const float*)d_in[15];
    const float* Wcb    = (const float*)d_in[16];
    const float* n1g    = (const float*)d_in[17];
    const float* n1b    = (const float*)d_in[18];
    const float* fW1    = (const float*)d_in[19];
    const float* fb1    = (const float*)d_in[20];
    const float* fW2    = (const float*)d_in[21];
    const float* fb2    = (const float*)d_in[22];
    const float* n2g    = (const float*)d_in[23];
    const float* n2b    = (const float*)d_in[24];
    const float* dWqloc = (const float*)d_in[25];
    const float* dWqrt  = (const float*)d_in[26];
    const float* dWk    = (const float*)d_in[27];
    const float* dWv    = (const float*)d_in[28];
    const float* dWc    = (const float*)d_in[29];
    const float* dWcb   = (const float*)d_in[30];
    float* out = (float*)d_out;

    float *px, *py, *pflag, *psn;
    SYM(px, g_x); SYM(py, g_y); SYM(pflag, g_flag); SYM(psn, g_sn);

    bf16 *pxh,*pxl, *px1h,*px1l, *pmhh,*pmhl, *pffhh,*pffhl, *pattnh,*pattnl;
    bf16 *pqkvh,*pqkvl, *pkvdh,*pkvdl, *pqlch,*pqlcl, *pqrth,*pqrtl;
    bf16 *pscoreh,*pscorel, *pcatlh,*pcatll, *pcatrh,*pcatrl;
    bf16 *pwqkvh,*pwqkvl, *pwch,*pwcl, *pf1h,*pf1l, *pf2h,*pf2l;
    bf16 *pwkvh,*pwkvl, *pwqlh,*pwqll, *pwpah,*pwpal, *pwdch,*pwdcl;
    SYM(pxh, g_xh); SYM(pxl, g_xl); SYM(px1h, g_x1h); SYM(px1l, g_x1l);
    SYM(pmhh, g_mhh); SYM(pmhl, g_mhl); SYM(pffhh, g_ffhh); SYM(pffhl, g_ffhl);
    SYM(pattnh, g_attnh); SYM(pattnl, g_attnl);
    SYM(pqkvh, g_qkvh); SYM(pqkvl, g_qkvl);
    SYM(pkvdh, g_kvdh); SYM(pkvdl, g_kvdl);
    SYM(pqlch, g_qlch); SYM(pqlcl, g_qlcl);
    SYM(pqrth, g_qrth); SYM(pqrtl, g_qrtl);
    SYM(pscoreh, g_scoreh); SYM(pscorel, g_scorel);
    SYM(pcatlh, g_catlh); SYM(pcatll, g_catll); SYM(pcatrh, g_catrh); SYM(pcatrl, g_catrl);
    SYM(pwqkvh, g_wqkvh); SYM(pwqkvl, g_wqkvl); SYM(pwch, g_wch); SYM(pwcl, g_wcl);
    SYM(pf1h, g_f1h); SYM(pf1l, g_f1l); SYM(pf2h, g_f2h); SYM(pf2l, g_f2l);
    SYM(pwkvh, g_wkvh); SYM(pwkvl, g_wkvl); SYM(pwqlh, g_wqlh); SYM(pwqll, g_wqll);
    SYM(pwpah, g_wpah); SYM(pwpal, g_wpal); SYM(pwdch, g_wdch); SYM(pwdcl, g_wdcl);

    const int R = BB * NN;
    const int TOT = BB * NN * EE;
    static int smem_set = 0;
    if (!smem_set) {
        cudaFuncSetAttribute(attn_mma, cudaFuncAttributeMaxDynamicSharedMemorySize, ATTN2_SMEM);
        cudaFuncSetAttribute(gemm_tc2, cudaFuncAttributeMaxDynamicSharedMemorySize, GEMM_SMEM);
        smem_set = 1;
    }

    // ---- launches 0-2 ----
    embed_kernel<<<(TOT + 255)/256, 256>>>(depot, cust, edW, edb, ecW, ecb);
    pack_w<<<(NLL*384*EE + 256*EE + 255)/256, 256>>>(Wq, Wk, Wv, dWk, dWv);
    cvt_split<<<(NLL*EE*EE + 255)/256, 256>>>(Wc,  pwch, pwcl, NLL*EE*EE);

    // ---- my launch 3: layer-0 QKV GEMM — ncu -s 5 target ----
    launch_tc(pxh, pxl, pwqkvh, pwqkvl, 0, 0, 0, 0, pqkvh, pqkvl,
              R, EE, 384, 1, 0, 0, 0, 0);

    padw_kernel<<<(EE*KRT + 255)/256, 256>>>(dWqrt);
    cvt_split<<<(NLL*FFHH*EE + 255)/256, 256>>>(fW1, pf1h, pf1l, NLL*FFHH*EE);
    cvt_split<<<(NLL*EE*FFHH + 255)/256, 256>>>(fW2, pf2h, pf2l, NLL*EE*FFHH);
    cvt_split<<<(EE*256 + 255)/256, 256>>>(dWqloc, pwqlh, pwqll, EE*256);
    cvt_split<<<(EE*EE + 255)/256, 256>>>(dWc, pwdch, pwdcl, EE*EE);

    // ---- encoder ----
    for (int i = 0; i < NLL; i++) {
        if (i > 0)
            launch_tc(pxh, pxl, pwqkvh + (long)i*384*EE, pwqkvl + (long)i*384*EE,
                      0, 0, 0, 0, pqkvh, pqkvl, R, EE, 384, 1, 0, 0, 0, 0);
        attn_mma<<<dim3(HH, BB), 256, ATTN2_SMEM>>>(
            pqkvh, pqkvl, (const bf16*)0, (const bf16*)0, (const float*)0, 384,
            pqkvh + 128, pqkvl + 128, 384, pqkvh + 256, pqkvl + 256, 384,
            (const float*)0, pmhh, pmhl);
        launch_tc(pmhh, pmhl, pwch + (long)i*EE*EE, pwcl + (long)i*EE*EE,
                  Wcb + (long)i*EE, pxh, pxl, py, 0, 0, R, EE, EE, 1, 0, 0, 0, 0);
        inorm_fused<<<dim3(BB, 4), 512>>>(py, n1g + (long)i*EE, n1b + (long)i*EE,
                                          (float*)0, px1h, px1l);
        launch_tc(px1h, px1l, pf1h + (long)i*FFHH*EE, pf1l + (long)i*FFHH*EE,
                  fb1 + (long)i*FFHH, 0, 0, 0, pffhh, pffhl, R, EE, FFHH, 1, 0, 0, 0, 1);
        launch_tc(pffhh, pffhl, pf2h + (long)i*EE*FFHH, pf2l + (long)i*EE*FFHH,
                  fb2 + (long)i*EE, px1h, px1l, py, 0, 0, R, FFHH, EE, 1, 0, 0, 0, 0);
        inorm_fused<<<dim3(BB, 4), 512>>>(py, n2g + (long)i*EE, n2b + (long)i*EE,
                                          (i == NLL-1) ? px : (float*)0, pxh, pxl);
    }

    // ---- decoder ----
    launch_tc(pxh, pxl, pwkvh, pwkvl, 0, 0, 0, 0, pkvdh, pkvdl,
              R, EE, 256, 1, 0, 0, 0, 0);
    build_cat<<<BB*MM, EE>>>(loadv, cur, subn, subl, sel, n2b + (long)(NLL-1)*EE);
    launch_tc(pcatlh, pcatll, pwqlh, pwqll, 0, 0, 0, 0, pqlch, pqlcl,
              R, 256, EE, 1, 0, 0, 0, 0);
    launch_tc(pcatrh, pcatrl, pwpah, pwpal, 0, 0, 0, 0, pqrth, pqrtl,
              R, KRT, EE, 1, 0, 0, 0, 0);
    attn_mma<<<dim3(HH, BB), 256, ATTN2_SMEM>>>(
        pqlch, pqlcl, pqrth, pqrtl, pflag, 128,
        pkvdh, pkvdl, 256, pkvdh + 128, pkvdl + 128, 256, mask, pattnh, pattnl);
    launch_tc(pattnh, pattnl, pwdch, pwdcl, dWcb, 0, 0, 0, pscoreh, pscorel,
              R, EE, EE, 1, 0, 0, 0, 0);
    launch_tc(pscoreh, pscorel, pxh, pxl, 0, 0, 0, psn, 0, 0, MM, EE, NN, BB,
              (long)MM*EE, (long)NN*EE, (long)MM*NN, 0);
    final_kernel<<<BB*MM, 256>>>(mask, out);
}

// round 14
// speedup vs baseline: 1.0055x; 1.0055x over previous
#include <cuda_runtime.h>
#include <cuda_bf16.h>
#include <math.h>
#include <stdint.h>

#define BB 32
#define NN 520
#define DEPOTN 20
#define CUSTN 500
#define EE 128
#define HH 8
#define DKK 16
#define FFHH 512
#define NLL 6
#define MM 520
#define LL 40
#define KRT 288

typedef __nv_bfloat16 bf16;

// ---------------- fp32 scratch ----------------
__device__ __align__(16) float g_x   [BB*NN*EE];
__device__ __align__(16) float g_qkv [BB*NN*384];
__device__ __align__(16) float g_y   [BB*NN*EE];
__device__ __align__(16) float g_x1  [BB*NN*EE];
__device__ __align__(16) float g_stats[BB*EE*2];
__device__ __align__(16) float g_kvd [BB*NN*256];
__device__ __align__(16) float g_qloc [BB*MM*EE];
__device__ __align__(16) float g_qrout[BB*MM*EE];
__device__ __align__(16) float g_flag [BB*MM];
__device__ __align__(16) float g_sn   [BB*MM*NN];

// ---------------- bf16 hi/lo scratch ----------------
__device__ __align__(16) bf16 g_xh[BB*NN*EE],      g_xl[BB*NN*EE];
__device__ __align__(16) bf16 g_x1h[BB*NN*EE],     g_x1l[BB*NN*EE];
__device__ __align__(16) bf16 g_mhh[BB*NN*EE],     g_mhl[BB*NN*EE];
__device__ __align__(16) bf16 g_ffhh[BB*NN*FFHH],  g_ffhl[BB*NN*FFHH];
__device__ __align__(16) bf16 g_attnh[BB*MM*EE],   g_attnl[BB*MM*EE];
__device__ __align__(16) bf16 g_scoreh[BB*MM*EE],  g_scorel[BB*MM*EE];
__device__ __align__(16) bf16 g_catlh[BB*MM*256],  g_catll[BB*MM*256];
__device__ __align__(16) bf16 g_catrh[BB*MM*KRT],  g_catrl[BB*MM*KRT];
__device__ __align__(16) bf16 g_wqkvh[NLL*384*EE], g_wqkvl[NLL*384*EE];
__device__ __align__(16) bf16 g_wch[NLL*EE*EE],    g_wcl[NLL*EE*EE];
__device__ __align__(16) bf16 g_f1h[NLL*FFHH*EE],  g_f1l[NLL*FFHH*EE];
__device__ __align__(16) bf16 g_f2h[NLL*EE*FFHH],  g_f2l[NLL*EE*FFHH];
__device__ __align__(16) bf16 g_wkvh[256*EE],      g_wkvl[256*EE];
__device__ __align__(16) bf16 g_wqlh[EE*256],      g_wqll[EE*256];
__device__ __align__(16) bf16 g_wpah[EE*KRT],      g_wpal[EE*KRT];
__device__ __align__(16) bf16 g_wdch[EE*EE],       g_wdcl[EE*EE];

__device__ __forceinline__ void split1(float x, bf16* h, bf16* l)
{
    bf16 hv = __float2bfloat16(x);
    *h = hv;
    *l = __float2bfloat16(x - __bfloat162float(hv));
}

__device__ __forceinline__ void cvtpk(float x0, float x1, uint32_t& h, uint32_t& l)
{
    bf16 h0 = __float2bfloat16(x0), h1 = __float2bfloat16(x1);
    float l0 = x0 - __bfloat162float(h0), l1 = x1 - __bfloat162float(h1);
    h = ((uint32_t)__bfloat16_as_ushort(h1) << 16) | __bfloat16_as_ushort(h0);
    bf16 g0 = __float2bfloat16(l0), g1 = __float2bfloat16(l1);
    l = ((uint32_t)__bfloat16_as_ushort(g1) << 16) | __bfloat16_as_ushort(g0);
}

// ---------------- generic fp32 -> hi/lo ----------------
__global__ void cvt_split(const float* __restrict__ s, bf16* __restrict__ h,
                          bf16* __restrict__ l, int n)
{
    int i = blockIdx.x * blockDim.x + threadIdx.x;
    if (i < n) split1(s[i], h + i, l + i);
}

// ---------------- embedding ----------------
__global__ void embed_kernel(const float* __restrict__ dep, const float* __restrict__ cus,
                             const float* __restrict__ Wd, const float* __restrict__ bd,
                             const float* __restrict__ Wc, const float* __restrict__ bc)
{
    int idx = blockIdx.x * blockDim.x + threadIdx.x;
    if (idx >= BB*NN*EE) return;
    int e = idx % EE;
    int n = (idx / EE) % NN;
    int b = idx / (EE*NN);
    float acc;
    if (n < DEPOTN) {
        const float* f = dep + ((long)b*DEPOTN + n) * 4;
        acc = bd[e];
        #pragma unroll
        for (int j = 0; j < 4; j++) acc += f[j] * Wd[e*4 + j];
    } else {
        const float* f = cus + ((long)b*CUSTN + (n - DEPOTN)) * 3;
        acc = bc[e];
        #pragma unroll
        for (int j = 0; j < 3; j++) acc += f[j] * Wc[e*3 + j];
    }
    g_x[idx] = acc;
    split1(acc, g_xh + idx, g_xl + idx);
}

// ---------------- weight packing ----------------
__global__ void pack_w(const float* __restrict__ Wq, const float* __restrict__ Wk,
                       const float* __restrict__ Wv, const float* __restrict__ dWk,
                       const float* __restrict__ dWv)
{
    int idx = blockIdx.x * blockDim.x + threadIdx.x;
    const int tot1 = NLL*384*EE;
    if (idx < tot1) {
        int col = idx % EE;
        int row = (idx / EE) % 384;
        int l   = idx / (EE*384);
        float v;
        if (row < 128)      v = Wq[((long)l*EE + row)*EE + col];
        else if (row < 256) v = Wk[((long)l*EE + row-128)*EE + col];
        else                v = Wv[((long)l*EE + row-256)*EE + col];
        split1(v, g_wqkvh + idx, g_wqkvl + idx);
    } else {
        int j = idx - tot1;
        if (j < 256*EE) {
            int col = j % EE;
            int row = j / EE;
            float v = (row < 128) ? dWk[row*EE + col] : dWv[(row-128)*EE + col];
            split1(v, g_wkvh + j, g_wkvl + j);
        }
    }
}

__global__ void padw_kernel(const float* __restrict__ Wr)
{
    int idx = blockIdx.x * blockDim.x + threadIdx.x;
    if (idx >= EE*KRT) return;
    int rr = idx / KRT, cc = idx % KRT;
    float v = (cc < 257) ? Wr[rr*257 + cc] : 0.f;
    split1(v, g_wpah + idx, g_wpal + idx);
}

// ---------------- MMA primitives ----------------
#define LDM4(r0,r1,r2,r3,addr) \
    asm volatile("ldmatrix.sync.aligned.m8n8.x4.shared.b16 {%0,%1,%2,%3},[%4];" \
                 : "=r"(r0),"=r"(r1),"=r"(r2),"=r"(r3) : "r"(addr))
#define LDM2(r0,r1,addr) \
    asm volatile("ldmatrix.sync.aligned.m8n8.x2.shared.b16 {%0,%1},[%2];" \
                 : "=r"(r0),"=r"(r1) : "r"(addr))
#define MMA16816(c,a,b) \
    asm volatile("mma.sync.aligned.m16n8k16.row.col.f32.bf16.bf16.f32 " \
                 "{%0,%1,%2,%3},{%4,%5,%6,%7},{%8,%9},{%0,%1,%2,%3};" \
                 : "+f"((c)[0]),"+f"((c)[1]),"+f"((c)[2]),"+f"((c)[3]) \
                 : "r"((a)[0]),"r"((a)[1]),"r"((a)[2]),"r"((a)[3]), "r"((b)[0]),"r"((b)[1]))

// ---------------- TC GEMM: pass-major, template-specialized epilogue ----------------
#define MAT 10240
#define STAGE 40960

template<bool WRITE_C, bool WRITE_HL>
__global__ __launch_bounds__(256, 2)
void gemm_tc2(const bf16* __restrict__ Ahi, const bf16* __restrict__ Alo,
              const bf16* __restrict__ Bhi, const bf16* __restrict__ Blo,
              const float* __restrict__ bias, const float* __restrict__ resid,
              float* __restrict__ C, bf16* __restrict__ Chi, bf16* __restrict__ Clo,
              int R, int K, int Cout, long sA, long sB, long sC, int relu)
{
    int bz = blockIdx.z;
    Ahi += (long)bz*sA; Alo += (long)bz*sA;
    Bhi += (long)bz*sB; Blo += (long)bz*sB;
    if (WRITE_C)  C   += (long)bz*sC;
    if (WRITE_HL) { Chi += (long)bz*sC; Clo += (long)bz*sC; }
    if (resid) resid += (long)bz*sC;

    extern __shared__ bf16 smb[];
    uint32_t sb = (uint32_t)__cvta_generic_to_shared(smb);

    int tid = threadIdx.x, lane = tid & 31, warp = tid >> 5;
    int wm = warp >> 2, wn = warp & 3;
    int rowBase = blockIdx.x * 128, colBase = blockIdx.y * 128;

    float c[4][4][4];
    #pragma unroll
    for (int i = 0; i < 4; i++)
        #pragma unroll
        for (int j = 0; j < 4; j++)
            { c[i][j][0]=0.f; c[i][j][1]=0.f; c[i][j][2]=0.f; c[i][j][3]=0.f; }

    const bf16* bases[4] = { Ahi, Alo, Bhi, Blo };
    int nk = K >> 5;

    #define FILL(st, kt) do { \
        int k0 = (kt) << 5; \
        _Pragma("unroll") \
        for (int t = 0; t < 8; t++) { \
            int o = tid + t*256; \
            int m = o >> 9, r = (o >> 2) & 127, seg = o & 3; \
            int gr = ((m < 2) ? rowBase : colBase) + r; \
            int lim = (m < 2) ? R : Cout; \
            long grc = (gr < lim) ? gr : 0; \
            const bf16* src = bases[m] + grc*K + k0 + seg*8; \
            uint32_t dst = sb + (st)*STAGE + m*MAT + r*80 + seg*16; \
            int nbytes = (gr < lim) ? 16 : 0; \
            asm volatile("cp.async.ca.shared.global [%0],[%1],16,%2;" \
                         :: "r"(dst), "l"(src), "r"(nbytes)); \
        } \
        asm volatile("cp.async.commit_group;"); \
    } while (0)

    FILL(0, 0);

    int ar = lane & 15, ak = (lane >> 4);
    int br = lane & 7,  bk = (lane >> 3) & 1;

    for (int kt = 0; kt < nk; kt++) {
        int st = kt & 1;
        if (kt + 1 < nk) {
            FILL(st ^ 1, kt + 1);
            asm volatile("cp.async.wait_group 1;");
        } else {
            asm volatile("cp.async.wait_group 0;");
        }
        __syncthreads();

        uint32_t aOff = sb + st*STAGE;
        uint32_t bOff = aOff + 2*MAT;
        #pragma unroll
        for (int ks = 0; ks < 2; ks++) {
            uint32_t Ah[4][4], Al[4][4];
            #pragma unroll
            for (int i = 0; i < 4; i++) {
                uint32_t ad = aOff + (uint32_t)((wm*64 + i*16 + ar)*80 + ak*16 + ks*32);
                LDM4(Ah[i][0], Ah[i][1], Ah[i][2], Ah[i][3], ad);
                LDM4(Al[i][0], Al[i][1], Al[i][2], Al[i][3], ad + MAT);
            }
            #pragma unroll
            for (int jp = 0; jp < 2; jp++) {
                uint32_t Bh[2][2], Bl[2][2];
                #pragma unroll
                for (int jj = 0; jj < 2; jj++) {
                    int j = jp*2 + jj;
                    uint32_t bd = bOff + (uint32_t)((wn*32 + j*8 + br)*80 + bk*16 + ks*32);
                    LDM2(Bh[jj][0], Bh[jj][1], bd);
                    LDM2(Bl[jj][0], Bl[jj][1], bd + MAT);
                }
                #pragma unroll
                for (int jj = 0; jj < 2; jj++)
                    #pragma unroll
                    for (int i = 0; i < 4; i++)
                        MMA16816(c[i][jp*2+jj], Ah[i], Bh[jj]);
                #pragma unroll
                for (int jj = 0; jj < 2; jj++)
                    #pragma unroll
                    for (int i = 0; i < 4; i++)
                        MMA16816(c[i][jp*2+jj], Ah[i], Bl[jj]);
                #pragma unroll
                for (int jj = 0; jj < 2; jj++)
                    #pragma unroll
                    for (int i = 0; i < 4; i++)
                        MMA16816(c[i][jp*2+jj], Al[i], Bh[jj]);
            }
        }
        __syncthreads();
    }

    int gid = lane >> 2, tig = lane & 3;
    #pragma unroll
    for (int i = 0; i < 4; i++) {
        int rbase = rowBase + wm*64 + i*16 + gid;
        #pragma unroll
        for (int j = 0; j < 4; j++) {
            int c0 = colBase + wn*32 + j*8 + tig*2;
            if (c0 >= Cout) continue;
            #pragma unroll
            for (int hh = 0; hh < 2; hh++) {
                int row = rbase + hh*8;
                if (row >= R) continue;
                float v0 = c[i][j][2*hh], v1 = c[i][j][2*hh+1];
                if (bias)  { v0 += bias[c0]; v1 += bias[c0+1]; }
                if (resid) {
                    float2 rv = *(const float2*)(resid + (long)row*Cout + c0);
                    v0 += rv.x; v1 += rv.y;
                }
                if (relu) { v0 = fmaxf(v0, 0.f); v1 = fmaxf(v1, 0.f); }
                if (WRITE_C)
                    *(float2*)(C + (long)row*Cout + c0) = make_float2(v0, v1);
                if (WRITE_HL) {
                    uint32_t hp, lp;
                    cvtpk(v0, v1, hp, lp);
                    *(uint32_t*)(Chi + (long)row*Cout + c0) = hp;
                    *(uint32_t*)(Clo + (long)row*Cout + c0) = lp;
                }
            }
        }
    }
}

// ---------------- attention: one block per (h,b); K/V staged ONCE, q-tiles looped ----------------
#define KPAD 576
#define KLO_B  27648
#define VHI_B  55296
#define VLO_B  18688
#define QHI_B  92672
#define QLO_B  6144
#define ATTN2_SMEM 104960
#define NQT 5

__global__ __launch_bounds__(256)
void attn_mma(const float* __restrict__ Q, const float* __restrict__ Q2,
              const float* __restrict__ flagv, int ldq,
              const float* __restrict__ Kt, int ldk,
              const float* __restrict__ Vt, int ldv,
              const float* __restrict__ mask,
              bf16* __restrict__ Oh, bf16* __restrict__ Ol)
{
    int h = blockIdx.x, b = blockIdx.y;
    extern __shared__ bf16 sm2[];
    uint32_t sb = (uint32_t)__cvta_generic_to_shared(sm2);
    int tid = threadIdx.x;

    const int KHI_E = 0, KLO_E = 13824, VHI_E = 27648, VLO_E = 36992;
    const int QHI_E = 46336, QLO_E = 49408;

    const float* Kg = Kt + (long)b*NN*ldk + h*DKK;
    const float* Vg = Vt + (long)b*NN*ldv + h*DKK;
    for (int i = tid; i < KPAD*DKK; i += 256) {
        int key = i >> 4, d = i & 15;
        float kv = (key < NN) ? Kg[(long)key*ldk + d] : 0.f;
        float vv = (key < NN) ? Vg[(long)key*ldv + d] : 0.f;
        bf16 kh = __float2bfloat16(kv);
        bf16 kl = __float2bfloat16(kv - __bfloat162float(kh));
        bf16 vh = __float2bfloat16(vv);
        bf16 vl = __float2bfloat16(vv - __bfloat162float(vh));
        sm2[KHI_E + key*24 + d] = kh;
        sm2[KLO_E + key*24 + d] = kl;
        sm2[VHI_E + d*584 + key] = vh;
        sm2[VLO_E + d*584 + key] = vl;
    }

    const float* Qg = Q + (long)b*NN*ldq + h*DKK;
    const float* Qg2 = Q2 ? (Q2 + (long)b*NN*ldq + h*DKK) : (const float*)0;

    int warp = tid >> 5, lane = tid & 31;
    int g = lane >> 2;
    int ar = lane & 15, ak = lane >> 4;
    int br = lane & 7,  bk = (lane >> 3) & 1;
    const unsigned FULL = 0xffffffffu;

    #pragma unroll 1
    for (int qt = 0; qt < NQT; qt++) {
        int qb = qt * 128;
        __syncthreads();
        for (int i = tid; i < 128*DKK; i += 256) {
            int row = i >> 4, d = i & 15;
            int q = qb + row;
            float qv = 0.f;
            if (q < NN) {
                qv = Qg[(long)q*ldq + d];
                if (Qg2) {
                    float f = flagv[(long)b*MM + q];
                    qv = f*qv + (1.f - f)*Qg2[(long)q*ldq + d];
                }
            }
            bf16 qh = __float2bfloat16(qv);
            sm2[QHI_E + row*24 + d] = qh;
            sm2[QLO_E + row*24 + d] = __float2bfloat16(qv - __bfloat162float(qh));
        }
        __syncthreads();

        if ((qb + warp*16) >= NN) continue;

        uint32_t Qh[4], Ql[4];
        {
            uint32_t qa = sb + QHI_B + (uint32_t)((warp*16 + ar)*48 + ak*16);
            LDM4(Qh[0], Qh[1], Qh[2], Qh[3], qa);
            LDM4(Ql[0], Ql[1], Ql[2], Ql[3], qa + QLO_B);
        }

        float oA[2][4], oB[2][4], oC[2][4];
        #pragma unroll
        for (int n = 0; n < 2; n++)
            #pragma unroll
            for (int q = 0; q < 4; q++) { oA[n][q]=0.f; oB[n][q]=0.f; oC[n][q]=0.f; }
        float mrow[2] = { -1e30f, -1e30f };
        float lrow[2] = { 0.f, 0.f };

        int qr0 = qb + warp*16 + g;
        int qm0 = (qr0 < NN) ? qr0 : NN-1;
        int qm1 = (qr0+8 < NN) ? qr0+8 : NN-1;
        const float* mk0 = mask ? (mask + ((long)(b*MM + qm0))*NN) : (const float*)0;
        const float* mk1 = mask ? (mask + ((long)(b*MM + qm1))*NN) : (const float*)0;

        #pragma unroll 1
        for (int c = 0; c < 9; c++) {
            float s[8][4];
            uint32_t Bh[8][2], Bl[8][2];
            #pragma unroll
            for (int t = 0; t < 8; t++) {
                uint32_t ka = sb + (uint32_t)((c*64 + t*8 + br)*48 + bk*16);
                LDM2(Bh[t][0], Bh[t][1], ka);
                LDM2(Bl[t][0], Bl[t][1], ka + KLO_B);
                s[t][0]=0.f; s[t][1]=0.f; s[t][2]=0.f; s[t][3]=0.f;
            }
            #pragma unroll
            for (int t = 0; t < 8; t++) MMA16816(s[t], Qh, Bh[t]);
            #pragma unroll
            for (int t = 0; t < 8; t++) MMA16816(s[t], Qh, Bl[t]);
            #pragma unroll
            for (int t = 0; t < 8; t++) MMA16816(s[t], Ql, Bh[t]);

            float mx0 = -1e30f, mx1 = -1e30f;
            #pragma unroll
            for (int t = 0; t < 8; t++) {
                if (c < 8 || t == 0) {
                    s[t][0]*=0.25f; s[t][1]*=0.25f; s[t][2]*=0.25f; s[t][3]*=0.25f;
                    if (mask) {
                        int j = c*64 + t*8 + (lane&3)*2;
                        float2 m0 = *(const float2*)(mk0 + j);
                        float2 m1 = *(const float2*)(mk1 + j);
                        s[t][0]+=m0.x; s[t][1]+=m0.y; s[t][2]+=m1.x; s[t][3]+=m1.y;
                    }
                } else {
                    s[t][0]=-1e30f; s[t][1]=-1e30f; s[t][2]=-1e30f; s[t][3]=-1e30f;
                }
                mx0 = fmaxf(mx0, fmaxf(s[t][0], s[t][1]));
                mx1 = fmaxf(mx1, fmaxf(s[t][2], s[t][3]));
            }
            mx0 = fmaxf(mx0, __shfl_xor_sync(FULL, mx0, 1));
            mx0 = fmaxf(mx0, __shfl_xor_sync(FULL, mx0, 2));
            mx1 = fmaxf(mx1, __shfl_xor_sync(FULL, mx1, 1));
            mx1 = fmaxf(mx1, __shfl_xor_sync(FULL, mx1, 2));
            float mn0 = fmaxf(mrow[0], mx0), mn1 = fmaxf(mrow[1], mx1);
            float f0 = __expf(mrow[0] - mn0), f1 = __expf(mrow[1] - mn1);
            mrow[0] = mn0; mrow[1] = mn1;
            float rs0 = 0.f, rs1 = 0.f;
            #pragma unroll
            for (int t = 0; t < 8; t++) {
                s[t][0] = __expf(s[t][0] - mn0);
                s[t][1] = __expf(s[t][1] - mn0);
                s[t][2] = __expf(s[t][2] - mn1);
                s[t][3] = __expf(s[t][3] - mn1);
                rs0 += s[t][0] + s[t][1];
                rs1 += s[t][2] + s[t][3];
            }
            rs0 += __shfl_xor_sync(FULL, rs0, 1); rs0 += __shfl_xor_sync(FULL, rs0, 2);
            rs1 += __shfl_xor_sync(FULL, rs1, 1); rs1 += __shfl_xor_sync(FULL, rs1, 2);
            lrow[0] = lrow[0]*f0 + rs0;
            lrow[1] = lrow[1]*f1 + rs1;
            #pragma unroll
            for (int n = 0; n < 2; n++) {
                oA[n][0]*=f0; oA[n][1]*=f0; oA[n][2]*=f1; oA[n][3]*=f1;
                oB[n][0]*=f0; oB[n][1]*=f0; oB[n][2]*=f1; oB[n][3]*=f1;
                oC[n][0]*=f0; oC[n][1]*=f0; oC[n][2]*=f1; oC[n][3]*=f1;
            }
            #pragma unroll
            for (int ss = 0; ss < 4; ss++) {
                uint32_t pah[4], pal[4];
                cvtpk(s[2*ss][0],   s[2*ss][1],   pah[0], pal[0]);
                cvtpk(s[2*ss][2],   s[2*ss][3],   pah[1], pal[1]);
                cvtpk(s[2*ss+1][0], s[2*ss+1][1], pah[2], pal[2]);
                cvtpk(s[2*ss+1][2], s[2*ss+1][3], pah[3], pal[3]);
                #pragma unroll
                for (int n = 0; n < 2; n++) {
                    uint32_t va = sb + VHI_B +
                        (uint32_t)((n*8 + br)*1168 + (c*64 + ss*16)*2 + bk*16);
                    uint32_t vh[2], vl[2];
                    LDM2(vh[0], vh[1], va);
                    LDM2(vl[0], vl[1], va + VLO_B);
                    MMA16816(oA[n], pah, vh);
                    MMA16816(oB[n], pah, vl);
                    MMA16816(oC[n], pal, vh);
                }
            }
        }

        float i0 = 1.f / lrow[0], i1 = 1.f / lrow[1];
        #pragma unroll
        for (int n = 0; n < 2; n++) {
            int d = h*DKK + n*8 + (lane&3)*2;
            if (qr0 < NN) {
                uint32_t hp, lp;
                cvtpk((oA[n][0]+oB[n][0]+oC[n][0])*i0,
                      (oA[n][1]+oB[n][1]+oC[n][1])*i0, hp, lp);
                long off = ((long)(b*NN + qr0))*EE + d;
                *(uint32_t*)(Oh + off) = hp;
                *(uint32_t*)(Ol + off) = lp;
            }
            if (qr0 + 8 < NN) {
                uint32_t hp, lp;
                cvtpk((oA[n][2]+oB[n][2]+oC[n][2])*i1,
                      (oA[n][3]+oB[n][3]+oC[n][3])*i1, hp, lp);
                long off = ((long)(b*NN + qr0 + 8))*EE + d;
                *(uint32_t*)(Oh + off) = hp;
                *(uint32_t*)(Ol + off) = lp;
            }
        }
    }
}

// ---------------- instance norm: high-parallelism fused stats ----------------
__global__ __launch_bounds__(512)
void inorm_sf2(const float* __restrict__ Y)
{
    int b = blockIdx.x, eg = blockIdx.y;
    int tid = threadIdx.x;
    int el = tid & 31, nch = tid >> 5;
    int e = eg*32 + el;
    float s1 = 0.f, s2 = 0.f;
    for (int n = nch; n < NN; n += 16) {
        float v = Y[((long)(b*NN + n))*EE + e];
        s1 += v; s2 += v*v;
    }
    __shared__ float sh1[512], sh2[512];
    sh1[tid] = s1; sh2[tid] = s2;
    __syncthreads();
    #pragma unroll
    for (int off = 256; off >= 32; off >>= 1) {
        if (tid < off) { sh1[tid] += sh1[tid+off]; sh2[tid] += sh2[tid+off]; }
        __syncthreads();
    }
    if (tid < 32) {
        float t1 = sh1[tid], t2 = sh2[tid];
        float mean = t1 / (float)NN;
        float var  = t2 / (float)NN - mean*mean;
        int ee = eg*32 + tid;
        g_stats[(b*EE+ee)*2]   = mean;
        g_stats[(b*EE+ee)*2+1] = rsqrtf(var + 1e-5f);
    }
}

// float4-vectorized apply
__global__ void inorm_apply(const float* __restrict__ Y, const float* __restrict__ gg,
                            const float* __restrict__ bt, float* __restrict__ Xo,
                            bf16* __restrict__ Xh, bf16* __restrict__ Xl)
{
    int i4 = blockIdx.x * blockDim.x + threadIdx.x;
    if (i4 >= BB*NN*EE/4) return;
    long idx = (long)i4 * 4;
    int e = (int)(idx % EE);
    int b = (int)(idx / ((long)NN*EE));
    float4 y = *(const float4*)(Y + idx);
    const float* st = g_stats + ((long)b*EE + e)*2;
    float v0 = (y.x - st[0]) * st[1] * gg[e]   + bt[e];
    float v1 = (y.y - st[2]) * st[3] * gg[e+1] + bt[e+1];
    float v2 = (y.z - st[4]) * st[5] * gg[e+2] + bt[e+2];
    float v3 = (y.w - st[6]) * st[7] * gg[e+3] + bt[e+3];
    *(float4*)(Xo + idx) = make_float4(v0, v1, v2, v3);
    uint32_t h0, l0, h1, l1;
    cvtpk(v0, v1, h0, l0);
    cvtpk(v2, v3, h1, l1);
    *(uint2*)(Xh + idx) = make_uint2(h0, h1);
    *(uint2*)(Xl + idx) = make_uint2(l0, l1);
}

// ---------------- decoder helpers ----------------
__global__ void build_cat(const float* __restrict__ loadv, const int* __restrict__ cur,
                          const int* __restrict__ subn, const int* __restrict__ subl,
                          const int* __restrict__ sel, const float* __restrict__ encmean)
{
    int r = blockIdx.x;
    int b = r / MM;
    int e = threadIdx.x;
    int c = cur[r];
    float le = g_x[((long)(b*NN + c))*EE + e];

    int len = subl[r];
    const int* nodes = subn + (long)r*LL;
    float ssum = 0.f; int cnt = 0;
    for (int l = 0; l < LL; l++) {
        int nd = nodes[l];
        if (l < len && nd >= DEPOTN) {
            ssum += g_x[((long)(b*NN + nd))*EE + e];
            cnt++;
        }
    }
    float cntf = (cnt > 0) ? (float)cnt : 1.f;
    float smean = ssum / cntf;

    long bl = (long)r*256, br = (long)r*KRT;
    split1(le,    g_catlh + bl + e,       g_catll + bl + e);
    split1(smean, g_catlh + bl + 128 + e, g_catll + bl + 128 + e);
    split1(le,    g_catrh + br + e,       g_catrl + br + e);
    split1(encmean[e], g_catrh + br + 128 + e, g_catrl + br + 128 + e);
    if (e == 0) split1(loadv[r], g_catrh + br + 256, g_catrl + br + 256);
    if (e >= 1 && e < 32) { g_catrh[br + 256 + e] = __float2bfloat16(0.f);
                            g_catrl[br + 256 + e] = __float2bfloat16(0.f); }
    if (e == 0) {
        int s2 = sel[(long)r*4 + 2];
        g_flag[r] = (s2 >= DEPOTN && c < DEPOTN) ? 1.f : 0.f;
    }
}

// ---------------- final tanh-clip + mask + softmax ----------------
__global__ void final_kernel(const float* __restrict__ mask, float* __restrict__ out)
{
    int r = blockIdx.x;
    int tid = threadIdx.x;
    __shared__ float buf[NN];
    __shared__ float red[256];
    const float* sn = g_sn + (long)r*NN;
    const float* mk = mask + (long)r*NN;
    const float invs = 0.08838834764831845f;

    float lm = -1e30f;
    for (int j = tid; j < NN; j += 256) {
        float v = 10.f * tanhf(sn[j] * invs) + mk[j];
        buf[j] = v;
        lm = fmaxf(lm, v);
    }
    red[tid] = lm; __syncthreads();
    for (int off = 128; off > 0; off >>= 1) {
        if (tid < off) red[tid] = fmaxf(red[tid], red[tid+off]);
        __syncthreads();
    }
    float mx = red[0]; __syncthreads();

    float ls = 0.f;
    for (int j = tid; j < NN; j += 256) {
        float e0 = __expf(buf[j] - mx);
        buf[j] = e0; ls += e0;
    }
    red[tid] = ls; __syncthreads();
    for (int off = 128; off > 0; off >>= 1) {
        if (tid < off) red[tid] += red[tid+off];
        __syncthreads();
    }
    float inv = 1.f / red[0];
    for (int j = tid; j < NN; j += 256)
        out[(long)r*NN + j] = buf[j] * inv;
}

// ---------------- host ----------------
#define GEMM_SMEM 81920

static void launch_f32(const bf16* Ah, const bf16* Al, const bf16* Bh, const bf16* Bl,
                       const float* bias, const float* resid, float* C,
                       int R, int K, int Cout, int batch,
                       long sA, long sB, long sC, int relu)
{
    dim3 grid((R + 127) / 128, (Cout + 127) / 128, batch);
    gemm_tc2<true,false><<<grid, 256, GEMM_SMEM>>>(Ah, Al, Bh, Bl, bias, resid,
                                                   C, 0, 0, R, K, Cout, sA, sB, sC, relu);
}

static void launch_hl(const bf16* Ah, const bf16* Al, const bf16* Bh, const bf16* Bl,
                      const float* bias, bf16* Ch, bf16* Cl,
                      int R, int K, int Cout, int batch,
                      long sA, long sB, long sC, int relu)
{
    dim3 grid((R + 127) / 128, (Cout + 127) / 128, batch);
    gemm_tc2<false,true><<<grid, 256, GEMM_SMEM>>>(Ah, Al, Bh, Bl, bias, 0,
                                                   0, Ch, Cl, R, K, Cout, sA, sB, sC, relu);
}

#define SYM(p, s) cudaGetSymbolAddress((void**)&p, s)

extern "C" void kernel_launch(void* const* d_in, const int* in_sizes, int n_in,
                              void* d_out, int out_size)
{
    const float* depot  = (const float*)d_in[0];
    const float* cust   = (const float*)d_in[1];
    const float* mask   = (const float*)d_in[2];
    const float* loadv  = (const float*)d_in[3];
    const int*   cur    = (const int*)d_in[4];
    const int*   subn   = (const int*)d_in[5];
    const int*   subl   = (const int*)d_in[6];
    const int*   sel    = (const int*)d_in[7];
    const float* edW    = (const float*)d_in[8];
    const float* edb    = (const float*)d_in[9];
    const float* ecW    = (const float*)d_in[10];
    const float* ecb    = (const float*)d_in[11];
    const float* Wq     = (const float*)d_in[12];
    const float* Wk     = (const float*)d_in[13];
    const float* Wv     = (const float*)d_in[14];
    const float* Wc     = (const float*)d_in[15];
    const float* Wcb    = (const float*)d_in[16];
    const float* n1g    = (const float*)d_in[17];
    const float* n1b    = (const float*)d_in[18];
    const float* fW1    = (const float*)d_in[19];
    const float* fb1    = (const float*)d_in[20];
    const float* fW2    = (const float*)d_in[21];
    const float* fb2    = (const float*)d_in[22];
    const float* n2g    = (const float*)d_in[23];
    const float* n2b    = (const float*)d_in[24];
    const float* dWqloc = (const float*)d_in[25];
    const float* dWqrt  = (const float*)d_in[26];
    const float* dWk    = (const float*)d_in[27];
    const float* dWv    = (const float*)d_in[28];
    const float* dWc    = (const float*)d_in[29];
    const float* dWcb   = (const float*)d_in[30];
    float* out = (float*)d_out;

    float *px, *pqkv, *py, *px1, *pkvd, *pqloc, *pqrout, *pflag, *psn;
    SYM(px, g_x); SYM(pqkv, g_qkv); SYM(py, g_y); SYM(px1, g_x1);
    SYM(pkvd, g_kvd); SYM(pqloc, g_qloc); SYM(pqrout, g_qrout);
    SYM(pflag, g_flag); SYM(psn, g_sn);

    bf16 *pxh,*pxl, *px1h,*px1l, *pmhh,*pmhl, *pffhh,*pffhl, *pattnh,*pattnl;
    bf16 *pscoreh,*pscorel, *pcatlh,*pcatll, *pcatrh,*pcatrl;
    bf16 *pwqkvh,*pwqkvl, *pwch,*pwcl, *pf1h,*pf1l, *pf2h,*pf2l;
    bf16 *pwkvh,*pwkvl, *pwqlh,*pwqll, *pwpah,*pwpal, *pwdch,*pwdcl;
    SYM(pxh, g_xh); SYM(pxl, g_xl); SYM(px1h, g_x1h); SYM(px1l, g_x1l);
    SYM(pmhh, g_mhh); SYM(pmhl, g_mhl); SYM(pffhh, g_ffhh); SYM(pffhl, g_ffhl);
    SYM(pattnh, g_attnh); SYM(pattnl, g_attnl);
    SYM(pscoreh, g_scoreh); SYM(pscorel, g_scorel);
    SYM(pcatlh, g_catlh); SYM(pcatll, g_catll); SYM(pcatrh, g_catrh); SYM(pcatrl, g_catrl);
    SYM(pwqkvh, g_wqkvh); SYM(pwqkvl, g_wqkvl); SYM(pwch, g_wch); SYM(pwcl, g_wcl);
    SYM(pf1h, g_f1h); SYM(pf1l, g_f1l); SYM(pf2h, g_f2h); SYM(pf2l, g_f2l);
    SYM(pwkvh, g_wkvh); SYM(pwkvl, g_wkvl); SYM(pwqlh, g_wqlh); SYM(pwqll, g_wqll);
    SYM(pwpah, g_wpah); SYM(pwpal, g_wpal); SYM(pwdch, g_wdch); SYM(pwdcl, g_wdcl);

    const int R = BB * NN;
    const int TOT = BB * NN * EE;
    static int smem_set = 0;
    if (!smem_set) {
        cudaFuncSetAttribute(attn_mma, cudaFuncAttributeMaxDynamicSharedMemorySize, ATTN2_SMEM);
        cudaFuncSetAttribute(gemm_tc2<true,false>,
                             cudaFuncAttributeMaxDynamicSharedMemorySize, GEMM_SMEM);
        cudaFuncSetAttribute(gemm_tc2<false,true>,
                             cudaFuncAttributeMaxDynamicSharedMemorySize, GEMM_SMEM);
        smem_set = 1;
    }

    // ---- launches 0-2 ----
    embed_kernel<<<(TOT + 255)/256, 256>>>(depot, cust, edW, edb, ecW, ecb);
    pack_w<<<(NLL*384*EE + 256*EE + 255)/256, 256>>>(Wq, Wk, Wv, dWk, dWv);
    cvt_split<<<(NLL*EE*EE + 255)/256, 256>>>(Wc,  pwch, pwcl, NLL*EE*EE);

    // ---- my launch 3: layer-0 QKV GEMM — ncu -s 5 target ----
    launch_f32(pxh, pxl, pwqkvh, pwqkvl, 0, 0, pqkv, R, EE, 384, 1, 0, 0, 0, 0);

    padw_kernel<<<(EE*KRT + 255)/256, 256>>>(dWqrt);
    cvt_split<<<(NLL*FFHH*EE + 255)/256, 256>>>(fW1, pf1h, pf1l, NLL*FFHH*EE);
    cvt_split<<<(NLL*EE*FFHH + 255)/256, 256>>>(fW2, pf2h, pf2l, NLL*EE*FFHH);
    cvt_split<<<(EE*256 + 255)/256, 256>>>(dWqloc, pwqlh, pwqll, EE*256);
    cvt_split<<<(EE*EE + 255)/256, 256>>>(dWc, pwdch, pwdcl, EE*EE);

    // ---- encoder ----
    for (int i = 0; i < NLL; i++) {
        if (i > 0)
            launch_f32(pxh, pxl, pwqkvh + (long)i*384*EE, pwqkvl + (long)i*384*EE,
                       0, 0, pqkv, R, EE, 384, 1, 0, 0, 0, 0);
        attn_mma<<<dim3(HH, BB), 256, ATTN2_SMEM>>>(
            pqkv, (const float*)0, (const float*)0, 384,
            pqkv + 128, 384, pqkv + 256, 384, (const float*)0, pmhh, pmhl);
        launch_f32(pmhh, pmhl, pwch + (long)i*EE*EE, pwcl + (long)i*EE*EE,
                   Wcb + (long)i*EE, px, py, R, EE, EE, 1, 0, 0, 0, 0);
        inorm_sf2<<<dim3(BB, 4), 512>>>(py);
        inorm_apply<<<(TOT/4 + 255)/256, 256>>>(py, n1g + (long)i*EE, n1b + (long)i*EE,
                                                px1, px1h, px1l);
        launch_hl(px1h, px1l, pf1h + (long)i*FFHH*EE, pf1l + (long)i*FFHH*EE,
                  fb1 + (long)i*FFHH, pffhh, pffhl, R, EE, FFHH, 1, 0, 0, 0, 1);
        launch_f32(pffhh, pffhl, pf2h + (long)i*EE*FFHH, pf2l + (long)i*EE*FFHH,
                   fb2 + (long)i*EE, px1, py, R, FFHH, EE, 1, 0, 0, 0, 0);
        inorm_sf2<<<dim3(BB, 4), 512>>>(py);
        inorm_apply<<<(TOT/4 + 255)/256, 256>>>(py, n2g + (long)i*EE, n2b + (long)i*EE,
                                                px, pxh, pxl);
    }

    // ---- decoder ----
    launch_f32(pxh, pxl, pwkvh, pwkvl, 0, 0, pkvd, R, EE, 256, 1, 0, 0, 0, 0);
    build_cat<<<BB*MM, EE>>>(loadv, cur, subn, subl, sel, n2b + (long)(NLL-1)*EE);
    launch_f32(pcatlh, pcatll, pwqlh, pwqll, 0, 0, pqloc, R, 256, EE, 1, 0, 0, 0, 0);
    launch_f32(pcatrh, pcatrl, pwpah, pwpal, 0, 0, pqrout, R, KRT, EE, 1, 0, 0, 0, 0);
    attn_mma<<<dim3(HH, BB), 256, ATTN2_SMEM>>>(
        pqloc, pqrout, pflag, 128, pkvd, 256, pkvd + 128, 256, mask, pattnh, pattnl);
    launch_hl(pattnh, pattnl, pwdch, pwdcl, dWcb, pscoreh, pscorel,
              R, EE, EE, 1, 0, 0, 0, 0);
    launch_f32(pscoreh, pscorel, pxh, pxl, 0, 0, psn, MM, EE, NN, BB,
               (long)MM*EE, (long)NN*EE, (long)MM*NN, 0);
    final_kernel<<<BB*MM, 256>>>(mask, out);
}

// round 15
// speedup vs baseline: 1.0532x; 1.0474x over previous
#include <cuda_runtime.h>
#include <cuda_bf16.h>
#include <math.h>
#include <stdint.h>

#define BB 32
#define NN 520
#define DEPOTN 20
#define CUSTN 500
#define EE 128
#define HH 8
#define DKK 16
#define FFHH 512
#define NLL 6
#define MM 520
#define LL 40
#define KRT 288

typedef __nv_bfloat16 bf16;

// ---------------- fp32 scratch ----------------
__device__ __align__(16) float g_x   [BB*NN*EE];
__device__ __align__(16) float g_qkv [BB*NN*384];
__device__ __align__(16) float g_y   [BB*NN*EE];
__device__ __align__(16) float g_x1  [BB*NN*EE];
__device__ __align__(16) float g_stats[BB*EE*2];
__device__ __align__(16) float g_kvd [BB*NN*256];
__device__ __align__(16) float g_qloc [BB*MM*EE];
__device__ __align__(16) float g_qrout[BB*MM*EE];
__device__ __align__(16) float g_flag [BB*MM];
__device__ __align__(16) float g_sn   [BB*MM*NN];

// ---------------- bf16 hi/lo scratch ----------------
__device__ __align__(16) bf16 g_xh[BB*NN*EE],      g_xl[BB*NN*EE];
__device__ __align__(16) bf16 g_x1h[BB*NN*EE],     g_x1l[BB*NN*EE];
__device__ __align__(16) bf16 g_mhh[BB*NN*EE],     g_mhl[BB*NN*EE];
__device__ __align__(16) bf16 g_ffhh[BB*NN*FFHH],  g_ffhl[BB*NN*FFHH];
__device__ __align__(16) bf16 g_attnh[BB*MM*EE],   g_attnl[BB*MM*EE];
__device__ __align__(16) bf16 g_scoreh[BB*MM*EE],  g_scorel[BB*MM*EE];
__device__ __align__(16) bf16 g_catlh[BB*MM*256],  g_catll[BB*MM*256];
__device__ __align__(16) bf16 g_catrh[BB*MM*KRT],  g_catrl[BB*MM*KRT];
__device__ __align__(16) bf16 g_wqkvh[NLL*384*EE], g_wqkvl[NLL*384*EE];
__device__ __align__(16) bf16 g_wch[NLL*EE*EE],    g_wcl[NLL*EE*EE];
__device__ __align__(16) bf16 g_f1h[NLL*FFHH*EE],  g_f1l[NLL*FFHH*EE];
__device__ __align__(16) bf16 g_f2h[NLL*EE*FFHH],  g_f2l[NLL*EE*FFHH];
__device__ __align__(16) bf16 g_wkvh[256*EE],      g_wkvl[256*EE];
__device__ __align__(16) bf16 g_wqlh[EE*256],      g_wqll[EE*256];
__device__ __align__(16) bf16 g_wpah[EE*KRT],      g_wpal[EE*KRT];
__device__ __align__(16) bf16 g_wdch[EE*EE],       g_wdcl[EE*EE];

__device__ __forceinline__ void split1(float x, bf16* h, bf16* l)
{
    bf16 hv = __float2bfloat16(x);
    *h = hv;
    *l = __float2bfloat16(x - __bfloat162float(hv));
}

__device__ __forceinline__ void cvtpk(float x0, float x1, uint32_t& h, uint32_t& l)
{
    bf16 h0 = __float2bfloat16(x0), h1 = __float2bfloat16(x1);
    float l0 = x0 - __bfloat162float(h0), l1 = x1 - __bfloat162float(h1);
    h = ((uint32_t)__bfloat16_as_ushort(h1) << 16) | __bfloat16_as_ushort(h0);
    bf16 g0 = __float2bfloat16(l0), g1 = __float2bfloat16(l1);
    l = ((uint32_t)__bfloat16_as_ushort(g1) << 16) | __bfloat16_as_ushort(g0);
}

// ---------------- generic fp32 -> hi/lo ----------------
__global__ void cvt_split(const float* __restrict__ s, bf16* __restrict__ h,
                          bf16* __restrict__ l, int n)
{
    int i = blockIdx.x * blockDim.x + threadIdx.x;
    if (i < n) split1(s[i], h + i, l + i);
}

// ---------------- embedding ----------------
__global__ void embed_kernel(const float* __restrict__ dep, const float* __restrict__ cus,
                             const float* __restrict__ Wd, const float* __restrict__ bd,
                             const float* __restrict__ Wc, const float* __restrict__ bc)
{
    int idx = blockIdx.x * blockDim.x + threadIdx.x;
    if (idx >= BB*NN*EE) return;
    int e = idx % EE;
    int n = (idx / EE) % NN;
    int b = idx / (EE*NN);
    float acc;
    if (n < DEPOTN) {
        const float* f = dep + ((long)b*DEPOTN + n) * 4;
        acc = bd[e];
        #pragma unroll
        for (int j = 0; j < 4; j++) acc += f[j] * Wd[e*4 + j];
    } else {
        const float* f = cus + ((long)b*CUSTN + (n - DEPOTN)) * 3;
        acc = bc[e];
        #pragma unroll
        for (int j = 0; j < 3; j++) acc += f[j] * Wc[e*3 + j];
    }
    g_x[idx] = acc;
    split1(acc, g_xh + idx, g_xl + idx);
}

// ---------------- weight packing ----------------
__global__ void pack_w(const float* __restrict__ Wq, const float* __restrict__ Wk,
                       const float* __restrict__ Wv, const float* __restrict__ dWk,
                       const float* __restrict__ dWv)
{
    int idx = blockIdx.x * blockDim.x + threadIdx.x;
    const int tot1 = NLL*384*EE;
    if (idx < tot1) {
        int col = idx % EE;
        int row = (idx / EE) % 384;
        int l   = idx / (EE*384);
        float v;
        if (row < 128)      v = Wq[((long)l*EE + row)*EE + col];
        else if (row < 256) v = Wk[((long)l*EE + row-128)*EE + col];
        else                v = Wv[((long)l*EE + row-256)*EE + col];
        split1(v, g_wqkvh + idx, g_wqkvl + idx);
    } else {
        int j = idx - tot1;
        if (j < 256*EE) {
            int col = j % EE;
            int row = j / EE;
            float v = (row < 128) ? dWk[row*EE + col] : dWv[(row-128)*EE + col];
            split1(v, g_wkvh + j, g_wkvl + j);
        }
    }
}

__global__ void padw_kernel(const float* __restrict__ Wr)
{
    int idx = blockIdx.x * blockDim.x + threadIdx.x;
    if (idx >= EE*KRT) return;
    int rr = idx / KRT, cc = idx % KRT;
    float v = (cc < 257) ? Wr[rr*257 + cc] : 0.f;
    split1(v, g_wpah + idx, g_wpal + idx);
}

// ---------------- MMA primitives ----------------
#define LDM4(r0,r1,r2,r3,addr) \
    asm volatile("ldmatrix.sync.aligned.m8n8.x4.shared.b16 {%0,%1,%2,%3},[%4];" \
                 : "=r"(r0),"=r"(r1),"=r"(r2),"=r"(r3) : "r"(addr))
#define LDM2(r0,r1,addr) \
    asm volatile("ldmatrix.sync.aligned.m8n8.x2.shared.b16 {%0,%1},[%2];" \
                 : "=r"(r0),"=r"(r1) : "r"(addr))
#define MMA16816(c,a,b) \
    asm volatile("mma.sync.aligned.m16n8k16.row.col.f32.bf16.bf16.f32 " \
                 "{%0,%1,%2,%3},{%4,%5,%6,%7},{%8,%9},{%0,%1,%2,%3};" \
                 : "+f"((c)[0]),"+f"((c)[1]),"+f"((c)[2]),"+f"((c)[3]) \
                 : "r"((a)[0]),"r"((a)[1]),"r"((a)[2]),"r"((a)[3]), "r"((b)[0]),"r"((b)[1]))

// ---------------- TC GEMM: pass-major, templated tile-M + epilogue ----------------
// TM in {128, 64}. Tile = TM x 128. 8 warps: wm in {0,1} covers TM/2 rows, wn in 0..3.
template<int TM, bool WRITE_C, bool WRITE_HL>
__global__ __launch_bounds__(256, 2)
void gemm_tc2(const bf16* __restrict__ Ahi, const bf16* __restrict__ Alo,
              const bf16* __restrict__ Bhi, const bf16* __restrict__ Blo,
              const float* __restrict__ bias, const float* __restrict__ resid,
              float* __restrict__ C, bf16* __restrict__ Chi, bf16* __restrict__ Clo,
              int R, int K, int Cout, long sA, long sB, long sC, int relu)
{
    constexpr int NI    = TM / 32;          // A 16-row chunks per warp
    constexpr int MATA  = TM * 80;          // bytes per A matrix tile
    constexpr int BOFF  = 2 * MATA;
    constexpr int BOFFL = 2 * MATA + 10240;
    constexpr int STG   = 2 * MATA + 20480; // bytes per stage
    constexpr int NOPS  = (2*TM + 256) * 4 / 256;  // cp.async per thread per stage

    int bz = blockIdx.z;
    Ahi += (long)bz*sA; Alo += (long)bz*sA;
    Bhi += (long)bz*sB; Blo += (long)bz*sB;
    if (WRITE_C)  C   += (long)bz*sC;
    if (WRITE_HL) { Chi += (long)bz*sC; Clo += (long)bz*sC; }
    if (resid) resid += (long)bz*sC;

    extern __shared__ bf16 smb[];
    uint32_t sb = (uint32_t)__cvta_generic_to_shared(smb);

    int tid = threadIdx.x, lane = tid & 31, warp = tid >> 5;
    int wm = warp >> 2, wn = warp & 3;
    int rowBase = blockIdx.x * TM, colBase = blockIdx.y * 128;

    float c[NI][4][4];
    #pragma unroll
    for (int i = 0; i < NI; i++)
        #pragma unroll
        for (int j = 0; j < 4; j++)
            { c[i][j][0]=0.f; c[i][j][1]=0.f; c[i][j][2]=0.f; c[i][j][3]=0.f; }

    const bf16* bases[4] = { Ahi, Alo, Bhi, Blo };
    int nk = K >> 5;

    #define FILL(st, kt) do { \
        int k0 = (kt) << 5; \
        _Pragma("unroll") \
        for (int t = 0; t < NOPS; t++) { \
            int o = tid + t*256; \
            int ridx = o >> 2, seg = o & 3; \
            int m, r; \
            if (ridx < 2*TM) { m = ridx / TM; r = ridx % TM; } \
            else { int rr2 = ridx - 2*TM; m = 2 + (rr2 >> 7); r = rr2 & 127; } \
            int gr = ((m < 2) ? rowBase : colBase) + r; \
            int lim = (m < 2) ? R : Cout; \
            long grc = (gr < lim) ? gr : 0; \
            const bf16* src = bases[m] + grc*K + k0 + seg*8; \
            int doff = (m < 2) ? m*MATA : (BOFF + (m-2)*10240); \
            uint32_t dst = sb + (st)*STG + doff + r*80 + seg*16; \
            int nbytes = (gr < lim) ? 16 : 0; \
            asm volatile("cp.async.ca.shared.global [%0],[%1],16,%2;" \
                         :: "r"(dst), "l"(src), "r"(nbytes)); \
        } \
        asm volatile("cp.async.commit_group;"); \
    } while (0)

    FILL(0, 0);

    int ar = lane & 15, ak = (lane >> 4);
    int br = lane & 7,  bk = (lane >> 3) & 1;

    for (int kt = 0; kt < nk; kt++) {
        int st = kt & 1;
        if (kt + 1 < nk) {
            FILL(st ^ 1, kt + 1);
            asm volatile("cp.async.wait_group 1;");
        } else {
            asm volatile("cp.async.wait_group 0;");
        }
        __syncthreads();

        uint32_t aOff = sb + st*STG;
        uint32_t bOff = aOff + BOFF;
        #pragma unroll
        for (int ks = 0; ks < 2; ks++) {
            uint32_t Ah[NI][4], Al[NI][4];
            #pragma unroll
            for (int i = 0; i < NI; i++) {
                uint32_t ad = aOff + (uint32_t)((wm*(TM/2) + i*16 + ar)*80 + ak*16 + ks*32);
                LDM4(Ah[i][0], Ah[i][1], Ah[i][2], Ah[i][3], ad);
                LDM4(Al[i][0], Al[i][1], Al[i][2], Al[i][3], ad + MATA);
            }
            #pragma unroll
            for (int jp = 0; jp < 2; jp++) {
                uint32_t Bh[2][2], Bl[2][2];
                #pragma unroll
                for (int jj = 0; jj < 2; jj++) {
                    int j = jp*2 + jj;
                    uint32_t bd = bOff + (uint32_t)((wn*32 + j*8 + br)*80 + bk*16 + ks*32);
                    LDM2(Bh[jj][0], Bh[jj][1], bd);
                    LDM2(Bl[jj][0], Bl[jj][1], bd + 10240);
                }
                #pragma unroll
                for (int jj = 0; jj < 2; jj++)
                    #pragma unroll
                    for (int i = 0; i < NI; i++)
                        MMA16816(c[i][jp*2+jj], Ah[i], Bh[jj]);
                #pragma unroll
                for (int jj = 0; jj < 2; jj++)
                    #pragma unroll
                    for (int i = 0; i < NI; i++)
                        MMA16816(c[i][jp*2+jj], Ah[i], Bl[jj]);
                #pragma unroll
                for (int jj = 0; jj < 2; jj++)
                    #pragma unroll
                    for (int i = 0; i < NI; i++)
                        MMA16816(c[i][jp*2+jj], Al[i], Bh[jj]);
            }
        }
        __syncthreads();
    }

    int gid = lane >> 2, tig = lane & 3;
    #pragma unroll
    for (int i = 0; i < NI; i++) {
        int rbase = rowBase + wm*(TM/2) + i*16 + gid;
        #pragma unroll
        for (int j = 0; j < 4; j++) {
            int c0 = colBase + wn*32 + j*8 + tig*2;
            if (c0 >= Cout) continue;
            #pragma unroll
            for (int hh = 0; hh < 2; hh++) {
                int row = rbase + hh*8;
                if (row >= R) continue;
                float v0 = c[i][j][2*hh], v1 = c[i][j][2*hh+1];
                if (bias)  { v0 += bias[c0]; v1 += bias[c0+1]; }
                if (resid) {
                    float2 rv = *(const float2*)(resid + (long)row*Cout + c0);
                    v0 += rv.x; v1 += rv.y;
                }
                if (relu) { v0 = fmaxf(v0, 0.f); v1 = fmaxf(v1, 0.f); }
                if (WRITE_C)
                    *(float2*)(C + (long)row*Cout + c0) = make_float2(v0, v1);
                if (WRITE_HL) {
                    uint32_t hp, lp;
                    cvtpk(v0, v1, hp, lp);
                    *(uint32_t*)(Chi + (long)row*Cout + c0) = hp;
                    *(uint32_t*)(Clo + (long)row*Cout + c0) = lp;
                }
            }
        }
    }
}

// ---------------- attention: one block per (h,b); K/V staged ONCE, q-tiles looped ----------------
#define KPAD 576
#define KLO_B  27648
#define VHI_B  55296
#define VLO_B  18688
#define QHI_B  92672
#define QLO_B  6144
#define ATTN2_SMEM 104960
#define NQT 5

__global__ __launch_bounds__(256)
void attn_mma(const float* __restrict__ Q, const float* __restrict__ Q2,
              const float* __restrict__ flagv, int ldq,
              const float* __restrict__ Kt, int ldk,
              const float* __restrict__ Vt, int ldv,
              const float* __restrict__ mask,
              bf16* __restrict__ Oh, bf16* __restrict__ Ol)
{
    int h = blockIdx.x, b = blockIdx.y;
    extern __shared__ bf16 sm2[];
    uint32_t sb = (uint32_t)__cvta_generic_to_shared(sm2);
    int tid = threadIdx.x;

    const int KHI_E = 0, KLO_E = 13824, VHI_E = 27648, VLO_E = 36992;
    const int QHI_E = 46336, QLO_E = 49408;

    const float* Kg = Kt + (long)b*NN*ldk + h*DKK;
    const float* Vg = Vt + (long)b*NN*ldv + h*DKK;
    for (int i = tid; i < KPAD*DKK; i += 256) {
        int key = i >> 4, d = i & 15;
        float kv = (key < NN) ? Kg[(long)key*ldk + d] : 0.f;
        float vv = (key < NN) ? Vg[(long)key*ldv + d] : 0.f;
        bf16 kh = __float2bfloat16(kv);
        bf16 kl = __float2bfloat16(kv - __bfloat162float(kh));
        bf16 vh = __float2bfloat16(vv);
        bf16 vl = __float2bfloat16(vv - __bfloat162float(vh));
        sm2[KHI_E + key*24 + d] = kh;
        sm2[KLO_E + key*24 + d] = kl;
        sm2[VHI_E + d*584 + key] = vh;
        sm2[VLO_E + d*584 + key] = vl;
    }

    const float* Qg = Q + (long)b*NN*ldq + h*DKK;
    const float* Qg2 = Q2 ? (Q2 + (long)b*NN*ldq + h*DKK) : (const float*)0;

    int warp = tid >> 5, lane = tid & 31;
    int g = lane >> 2;
    int ar = lane & 15, ak = lane >> 4;
    int br = lane & 7,  bk = (lane >> 3) & 1;
    const unsigned FULL = 0xffffffffu;

    #pragma unroll 1
    for (int qt = 0; qt < NQT; qt++) {
        int qb = qt * 128;
        __syncthreads();
        for (int i = tid; i < 128*DKK; i += 256) {
            int row = i >> 4, d = i & 15;
            int q = qb + row;
            float qv = 0.f;
            if (q < NN) {
                qv = Qg[(long)q*ldq + d];
                if (Qg2) {
                    float f = flagv[(long)b*MM + q];
                    qv = f*qv + (1.f - f)*Qg2[(long)q*ldq + d];
                }
            }
            bf16 qh = __float2bfloat16(qv);
            sm2[QHI_E + row*24 + d] = qh;
            sm2[QLO_E + row*24 + d] = __float2bfloat16(qv - __bfloat162float(qh));
        }
        __syncthreads();

        if ((qb + warp*16) >= NN) continue;

        uint32_t Qh[4], Ql[4];
        {
            uint32_t qa = sb + QHI_B + (uint32_t)((warp*16 + ar)*48 + ak*16);
            LDM4(Qh[0], Qh[1], Qh[2], Qh[3], qa);
            LDM4(Ql[0], Ql[1], Ql[2], Ql[3], qa + QLO_B);
        }

        float oA[2][4], oB[2][4], oC[2][4];
        #pragma unroll
        for (int n = 0; n < 2; n++)
            #pragma unroll
            for (int q = 0; q < 4; q++) { oA[n][q]=0.f; oB[n][q]=0.f; oC[n][q]=0.f; }
        float mrow[2] = { -1e30f, -1e30f };
        float lrow[2] = { 0.f, 0.f };

        int qr0 = qb + warp*16 + g;
        int qm0 = (qr0 < NN) ? qr0 : NN-1;
        int qm1 = (qr0+8 < NN) ? qr0+8 : NN-1;
        const float* mk0 = mask ? (mask + ((long)(b*MM + qm0))*NN) : (const float*)0;
        const float* mk1 = mask ? (mask + ((long)(b*MM + qm1))*NN) : (const float*)0;

        #pragma unroll 1
        for (int c = 0; c < 9; c++) {
            float s[8][4];
            uint32_t Bh[8][2], Bl[8][2];
            #pragma unroll
            for (int t = 0; t < 8; t++) {
                uint32_t ka = sb + (uint32_t)((c*64 + t*8 + br)*48 + bk*16);
                LDM2(Bh[t][0], Bh[t][1], ka);
                LDM2(Bl[t][0], Bl[t][1], ka + KLO_B);
                s[t][0]=0.f; s[t][1]=0.f; s[t][2]=0.f; s[t][3]=0.f;
            }
            #pragma unroll
            for (int t = 0; t < 8; t++) MMA16816(s[t], Qh, Bh[t]);
            #pragma unroll
            for (int t = 0; t < 8; t++) MMA16816(s[t], Qh, Bl[t]);
            #pragma unroll
            for (int t = 0; t < 8; t++) MMA16816(s[t], Ql, Bh[t]);

            float mx0 = -1e30f, mx1 = -1e30f;
            #pragma unroll
            for (int t = 0; t < 8; t++) {
                if (c < 8 || t == 0) {
                    s[t][0]*=0.25f; s[t][1]*=0.25f; s[t][2]*=0.25f; s[t][3]*=0.25f;
                    if (mask) {
                        int j = c*64 + t*8 + (lane&3)*2;
                        float2 m0 = *(const float2*)(mk0 + j);
                        float2 m1 = *(const float2*)(mk1 + j);
                        s[t][0]+=m0.x; s[t][1]+=m0.y; s[t][2]+=m1.x; s[t][3]+=m1.y;
                    }
                } else {
                    s[t][0]=-1e30f; s[t][1]=-1e30f; s[t][2]=-1e30f; s[t][3]=-1e30f;
                }
                mx0 = fmaxf(mx0, fmaxf(s[t][0], s[t][1]));
                mx1 = fmaxf(mx1, fmaxf(s[t][2], s[t][3]));
            }
            mx0 = fmaxf(mx0, __shfl_xor_sync(FULL, mx0, 1));
            mx0 = fmaxf(mx0, __shfl_xor_sync(FULL, mx0, 2));
            mx1 = fmaxf(mx1, __shfl_xor_sync(FULL, mx1, 1));
            mx1 = fmaxf(mx1, __shfl_xor_sync(FULL, mx1, 2));
            float mn0 = fmaxf(mrow[0], mx0), mn1 = fmaxf(mrow[1], mx1);
            float f0 = __expf(mrow[0] - mn0), f1 = __expf(mrow[1] - mn1);
            mrow[0] = mn0; mrow[1] = mn1;
            float rs0 = 0.f, rs1 = 0.f;
            #pragma unroll
            for (int t = 0; t < 8; t++) {
                s[t][0] = __expf(s[t][0] - mn0);
                s[t][1] = __expf(s[t][1] - mn0);
                s[t][2] = __expf(s[t][2] - mn1);
                s[t][3] = __expf(s[t][3] - mn1);
                rs0 += s[t][0] + s[t][1];
                rs1 += s[t][2] + s[t][3];
            }
            rs0 += __shfl_xor_sync(FULL, rs0, 1); rs0 += __shfl_xor_sync(FULL, rs0, 2);
            rs1 += __shfl_xor_sync(FULL, rs1, 1); rs1 += __shfl_xor_sync(FULL, rs1, 2);
            lrow[0] = lrow[0]*f0 + rs0;
            lrow[1] = lrow[1]*f1 + rs1;
            #pragma unroll
            for (int n = 0; n < 2; n++) {
                oA[n][0]*=f0; oA[n][1]*=f0; oA[n][2]*=f1; oA[n][3]*=f1;
                oB[n][0]*=f0; oB[n][1]*=f0; oB[n][2]*=f1; oB[n][3]*=f1;
                oC[n][0]*=f0; oC[n][1]*=f0; oC[n][2]*=f1; oC[n][3]*=f1;
            }
            #pragma unroll
            for (int ss = 0; ss < 4; ss++) {
                uint32_t pah[4], pal[4];
                cvtpk(s[2*ss][0],   s[2*ss][1],   pah[0], pal[0]);
                cvtpk(s[2*ss][2],   s[2*ss][3],   pah[1], pal[1]);
                cvtpk(s[2*ss+1][0], s[2*ss+1][1], pah[2], pal[2]);
                cvtpk(s[2*ss+1][2], s[2*ss+1][3], pah[3], pal[3]);
                #pragma unroll
                for (int n = 0; n < 2; n++) {
                    uint32_t va = sb + VHI_B +
                        (uint32_t)((n*8 + br)*1168 + (c*64 + ss*16)*2 + bk*16);
                    uint32_t vh[2], vl[2];
                    LDM2(vh[0], vh[1], va);
                    LDM2(vl[0], vl[1], va + VLO_B);
                    MMA16816(oA[n], pah, vh);
                    MMA16816(oB[n], pah, vl);
                    MMA16816(oC[n], pal, vh);
                }
            }
        }

        float i0 = 1.f / lrow[0], i1 = 1.f / lrow[1];
        #pragma unroll
        for (int n = 0; n < 2; n++) {
            int d = h*DKK + n*8 + (lane&3)*2;
            if (qr0 < NN) {
                uint32_t hp, lp;
                cvtpk((oA[n][0]+oB[n][0]+oC[n][0])*i0,
                      (oA[n][1]+oB[n][1]+oC[n][1])*i0, hp, lp);
                long off = ((long)(b*NN + qr0))*EE + d;
                *(uint32_t*)(Oh + off) = hp;
                *(uint32_t*)(Ol + off) = lp;
            }
            if (qr0 + 8 < NN) {
                uint32_t hp, lp;
                cvtpk((oA[n][2]+oB[n][2]+oC[n][2])*i1,
                      (oA[n][3]+oB[n][3]+oC[n][3])*i1, hp, lp);
                long off = ((long)(b*NN + qr0 + 8))*EE + d;
                *(uint32_t*)(Oh + off) = hp;
                *(uint32_t*)(Ol + off) = lp;
            }
        }
    }
}

// ---------------- instance norm: high-parallelism fused stats ----------------
__global__ __launch_bounds__(512)
void inorm_sf2(const float* __restrict__ Y)
{
    int b = blockIdx.x, eg = blockIdx.y;
    int tid = threadIdx.x;
    int el = tid & 31, nch = tid >> 5;
    int e = eg*32 + el;
    float s1 = 0.f, s2 = 0.f;
    for (int n = nch; n < NN; n += 16) {
        float v = Y[((long)(b*NN + n))*EE + e];
        s1 += v; s2 += v*v;
    }
    __shared__ float sh1[512], sh2[512];
    sh1[tid] = s1; sh2[tid] = s2;
    __syncthreads();
    #pragma unroll
    for (int off = 256; off >= 32; off >>= 1) {
        if (tid < off) { sh1[tid] += sh1[tid+off]; sh2[tid] += sh2[tid+off]; }
        __syncthreads();
    }
    if (tid < 32) {
        float t1 = sh1[tid], t2 = sh2[tid];
        float mean = t1 / (float)NN;
        float var  = t2 / (float)NN - mean*mean;
        int ee = eg*32 + tid;
        g_stats[(b*EE+ee)*2]   = mean;
        g_stats[(b*EE+ee)*2+1] = rsqrtf(var + 1e-5f);
    }
}

// float4-vectorized apply
__global__ void inorm_apply(const float* __restrict__ Y, const float* __restrict__ gg,
                            const float* __restrict__ bt, float* __restrict__ Xo,
                            bf16* __restrict__ Xh, bf16* __restrict__ Xl)
{
    int i4 = blockIdx.x * blockDim.x + threadIdx.x;
    if (i4 >= BB*NN*EE/4) return;
    long idx = (long)i4 * 4;
    int e = (int)(idx % EE);
    int b = (int)(idx / ((long)NN*EE));
    float4 y = *(const float4*)(Y + idx);
    const float* st = g_stats + ((long)b*EE + e)*2;
    float v0 = (y.x - st[0]) * st[1] * gg[e]   + bt[e];
    float v1 = (y.y - st[2]) * st[3] * gg[e+1] + bt[e+1];
    float v2 = (y.z - st[4]) * st[5] * gg[e+2] + bt[e+2];
    float v3 = (y.w - st[6]) * st[7] * gg[e+3] + bt[e+3];
    *(float4*)(Xo + idx) = make_float4(v0, v1, v2, v3);
    uint32_t h0, l0, h1, l1;
    cvtpk(v0, v1, h0, l0);
    cvtpk(v2, v3, h1, l1);
    *(uint2*)(Xh + idx) = make_uint2(h0, h1);
    *(uint2*)(Xl + idx) = make_uint2(l0, l1);
}

// ---------------- decoder helpers ----------------
__global__ void build_cat(const float* __restrict__ loadv, const int* __restrict__ cur,
                          const int* __restrict__ subn, const int* __restrict__ subl,
                          const int* __restrict__ sel, const float* __restrict__ encmean)
{
    int r = blockIdx.x;
    int b = r / MM;
    int e = threadIdx.x;
    int c = cur[r];
    float le = g_x[((long)(b*NN + c))*EE + e];

    int len = subl[r];
    const int* nodes = subn + (long)r*LL;
    float ssum = 0.f; int cnt = 0;
    for (int l = 0; l < LL; l++) {
        int nd = nodes[l];
        if (l < len && nd >= DEPOTN) {
            ssum += g_x[((long)(b*NN + nd))*EE + e];
            cnt++;
        }
    }
    float cntf = (cnt > 0) ? (float)cnt : 1.f;
    float smean = ssum / cntf;

    long bl = (long)r*256, br = (long)r*KRT;
    split1(le,    g_catlh + bl + e,       g_catll + bl + e);
    split1(smean, g_catlh + bl + 128 + e, g_catll + bl + 128 + e);
    split1(le,    g_catrh + br + e,       g_catrl + br + e);
    split1(encmean[e], g_catrh + br + 128 + e, g_catrl + br + 128 + e);
    if (e == 0) split1(loadv[r], g_catrh + br + 256, g_catrl + br + 256);
    if (e >= 1 && e < 32) { g_catrh[br + 256 + e] = __float2bfloat16(0.f);
                            g_catrl[br + 256 + e] = __float2bfloat16(0.f); }
    if (e == 0) {
        int s2 = sel[(long)r*4 + 2];
        g_flag[r] = (s2 >= DEPOTN && c < DEPOTN) ? 1.f : 0.f;
    }
}

// ---------------- final tanh-clip + mask + softmax ----------------
__global__ void final_kernel(const float* __restrict__ mask, float* __restrict__ out)
{
    int r = blockIdx.x;
    int tid = threadIdx.x;
    __shared__ float buf[NN];
    __shared__ float red[256];
    const float* sn = g_sn + (long)r*NN;
    const float* mk = mask + (long)r*NN;
    const float invs = 0.08838834764831845f;

    float lm = -1e30f;
    for (int j = tid; j < NN; j += 256) {
        float v = 10.f * tanhf(sn[j] * invs) + mk[j];
        buf[j] = v;
        lm = fmaxf(lm, v);
    }
    red[tid] = lm; __syncthreads();
    for (int off = 128; off > 0; off >>= 1) {
        if (tid < off) red[tid] = fmaxf(red[tid], red[tid+off]);
        __syncthreads();
    }
    float mx = red[0]; __syncthreads();

    float ls = 0.f;
    for (int j = tid; j < NN; j += 256) {
        float e0 = __expf(buf[j] - mx);
        buf[j] = e0; ls += e0;
    }
    red[tid] = ls; __syncthreads();
    for (int off = 128; off > 0; off >>= 1) {
        if (tid < off) red[tid] += red[tid+off];
        __syncthreads();
    }
    float inv = 1.f / red[0];
    for (int j = tid; j < NN; j += 256)
        out[(long)r*NN + j] = buf[j] * inv;
}

// ---------------- host ----------------
#define GEMM_SMEM_128 81920
#define GEMM_SMEM_64  61440

static void launch_f32_128(const bf16* Ah, const bf16* Al, const bf16* Bh, const bf16* Bl,
                           const float* bias, const float* resid, float* C,
                           int R, int K, int Cout, int batch,
                           long sA, long sB, long sC, int relu)
{
    dim3 grid((R + 127) / 128, (Cout + 127) / 128, batch);
    gemm_tc2<128,true,false><<<grid, 256, GEMM_SMEM_128>>>(Ah, Al, Bh, Bl, bias, resid,
                                                           C, 0, 0, R, K, Cout, sA, sB, sC, relu);
}
static void launch_f32_64(const bf16* Ah, const bf16* Al, const bf16* Bh, const bf16* Bl,
                          const float* bias, const float* resid, float* C,
                          int R, int K, int Cout, int batch,
                          long sA, long sB, long sC, int relu)
{
    dim3 grid((R + 63) / 64, (Cout + 127) / 128, batch);
    gemm_tc2<64,true,false><<<grid, 256, GEMM_SMEM_64>>>(Ah, Al, Bh, Bl, bias, resid,
                                                         C, 0, 0, R, K, Cout, sA, sB, sC, relu);
}
static void launch_hl_128(const bf16* Ah, const bf16* Al, const bf16* Bh, const bf16* Bl,
                          const float* bias, bf16* Ch, bf16* Cl,
                          int R, int K, int Cout, int batch,
                          long sA, long sB, long sC, int relu)
{
    dim3 grid((R + 127) / 128, (Cout + 127) / 128, batch);
    gemm_tc2<128,false,true><<<grid, 256, GEMM_SMEM_128>>>(Ah, Al, Bh, Bl, bias, 0,
                                                           0, Ch, Cl, R, K, Cout, sA, sB, sC, relu);
}
static void launch_hl_64(const bf16* Ah, const bf16* Al, const bf16* Bh, const bf16* Bl,
                         const float* bias, bf16* Ch, bf16* Cl,
                         int R, int K, int Cout, int batch,
                         long sA, long sB, long sC, int relu)
{
    dim3 grid((R + 63) / 64, (Cout + 127) / 128, batch);
    gemm_tc2<64,false,true><<<grid, 256, GEMM_SMEM_64>>>(Ah, Al, Bh, Bl, bias, 0,
                                                         0, Ch, Cl, R, K, Cout, sA, sB, sC, relu);
}

#define SYM(p, s) cudaGetSymbolAddress((void**)&p, s)

extern "C" void kernel_launch(void* const* d_in, const int* in_sizes, int n_in,
                              void* d_out, int out_size)
{
    const float* depot  = (const float*)d_in[0];
    const float* cust   = (const float*)d_in[1];
    const float* mask   = (const float*)d_in[2];
    const float* loadv  = (const float*)d_in[3];
    const int*   cur    = (const int*)d_in[4];
    const int*   subn   = (const int*)d_in[5];
    const int*   subl   = (const int*)d_in[6];
    const int*   sel    = (const int*)d_in[7];
    const float* edW    = (const float*)d_in[8];
    const float* edb    = (const float*)d_in[9];
    const float* ecW    = (const float*)d_in[10];
    const float* ecb    = (const float*)d_in[11];
    const float* Wq     = (const float*)d_in[12];
    const float* Wk     = (const float*)d_in[13];
    const float* Wv     = (const float*)d_in[14];
    const float* Wc     = (const float*)d_in[15];
    const float* Wcb    = (const float*)d_in[16];
    const float* n1g    = (const float*)d_in[17];
    const float* n1b    = (const float*)d_in[18];
    const float* fW1    = (const float*)d_in[19];
    const float* fb1    = (const float*)d_in[20];
    const float* fW2    = (const float*)d_in[21];
    const float* fb2    = (const float*)d_in[22];
    const float* n2g    = (const float*)d_in[23];
    const float* n2b    = (const float*)d_in[24];
    const float* dWqloc = (const float*)d_in[25];
    const float* dWqrt  = (const float*)d_in[26];
    const float* dWk    = (const float*)d_in[27];
    const float* dWv    = (const float*)d_in[28];
    const float* dWc    = (const float*)d_in[29];
    const float* dWcb   = (const float*)d_in[30];
    float* out = (float*)d_out;

    float *px, *pqkv, *py, *px1, *pkvd, *pqloc, *pqrout, *pflag, *psn;
    SYM(px, g_x); SYM(pqkv, g_qkv); SYM(py, g_y); SYM(px1, g_x1);
    SYM(pkvd, g_kvd); SYM(pqloc, g_qloc); SYM(pqrout, g_qrout);
    SYM(pflag, g_flag); SYM(psn, g_sn);

    bf16 *pxh,*pxl, *px1h,*px1l, *pmhh,*pmhl, *pffhh,*pffhl, *pattnh,*pattnl;
    bf16 *pscoreh,*pscorel, *pcatlh,*pcatll, *pcatrh,*pcatrl;
    bf16 *pwqkvh,*pwqkvl, *pwch,*pwcl, *pf1h,*pf1l, *pf2h,*pf2l;
    bf16 *pwkvh,*pwkvl, *pwqlh,*pwqll, *pwpah,*pwpal, *pwdch,*pwdcl;
    SYM(pxh, g_xh); SYM(pxl, g_xl); SYM(px1h, g_x1h); SYM(px1l, g_x1l);
    SYM(pmhh, g_mhh); SYM(pmhl, g_mhl); SYM(pffhh, g_ffhh); SYM(pffhl, g_ffhl);
    SYM(pattnh, g_attnh); SYM(pattnl, g_attnl);
    SYM(pscoreh, g_scoreh); SYM(pscorel, g_scorel);
    SYM(pcatlh, g_catlh); SYM(pcatll, g_catll); SYM(pcatrh, g_catrh); SYM(pcatrl, g_catrl);
    SYM(pwqkvh, g_wqkvh); SYM(pwqkvl, g_wqkvl); SYM(pwch, g_wch); SYM(pwcl, g_wcl);
    SYM(pf1h, g_f1h); SYM(pf1l, g_f1l); SYM(pf2h, g_f2h); SYM(pf2l, g_f2l);
    SYM(pwkvh, g_wkvh); SYM(pwkvl, g_wkvl); SYM(pwqlh, g_wqlh); SYM(pwqll, g_wqll);
    SYM(pwpah, g_wpah); SYM(pwpal, g_wpal); SYM(pwdch, g_wdch); SYM(pwdcl, g_wdcl);

    const int R = BB * NN;
    const int TOT = BB * NN * EE;
    static int smem_set = 0;
    if (!smem_set) {
        cudaFuncSetAttribute(attn_mma, cudaFuncAttributeMaxDynamicSharedMemorySize, ATTN2_SMEM);
        cudaFuncSetAttribute(gemm_tc2<128,true,false>,
                             cudaFuncAttributeMaxDynamicSharedMemorySize, GEMM_SMEM_128);
        cudaFuncSetAttribute(gemm_tc2<128,false,true>,
                             cudaFuncAttributeMaxDynamicSharedMemorySize, GEMM_SMEM_128);
        cudaFuncSetAttribute(gemm_tc2<64,true,false>,
                             cudaFuncAttributeMaxDynamicSharedMemorySize, GEMM_SMEM_64);
        cudaFuncSetAttribute(gemm_tc2<64,false,true>,
                             cudaFuncAttributeMaxDynamicSharedMemorySize, GEMM_SMEM_64);
        smem_set = 1;
    }

    // ---- launches 0-2 ----
    embed_kernel<<<(TOT + 255)/256, 256>>>(depot, cust, edW, edb, ecW, ecb);
    pack_w<<<(NLL*384*EE + 256*EE + 255)/256, 256>>>(Wq, Wk, Wv, dWk, dWv);
    cvt_split<<<(NLL*EE*EE + 255)/256, 256>>>(Wc,  pwch, pwcl, NLL*EE*EE);

    // ---- my launch 3: layer-0 QKV GEMM — ncu -s 5 target ----
    launch_f32_128(pxh, pxl, pwqkvh, pwqkvl, 0, 0, pqkv, R, EE, 384, 1, 0, 0, 0, 0);

    padw_kernel<<<(EE*KRT + 255)/256, 256>>>(dWqrt);
    cvt_split<<<(NLL*FFHH*EE + 255)/256, 256>>>(fW1, pf1h, pf1l, NLL*FFHH*EE);
    cvt_split<<<(NLL*EE*FFHH + 255)/256, 256>>>(fW2, pf2h, pf2l, NLL*EE*FFHH);
    cvt_split<<<(EE*256 + 255)/256, 256>>>(dWqloc, pwqlh, pwqll, EE*256);
    cvt_split<<<(EE*EE + 255)/256, 256>>>(dWc, pwdch, pwdcl, EE*EE);

    // ---- encoder ----
    for (int i = 0; i < NLL; i++) {
        if (i > 0)
            launch_f32_128(pxh, pxl, pwqkvh + (long)i*384*EE, pwqkvl + (long)i*384*EE,
                           0, 0, pqkv, R, EE, 384, 1, 0, 0, 0, 0);
        attn_mma<<<dim3(HH, BB), 256, ATTN2_SMEM>>>(
            pqkv, (const float*)0, (const float*)0, 384,
            pqkv + 128, 384, pqkv + 256, 384, (const float*)0, pmhh, pmhl);
        launch_f32_64(pmhh, pmhl, pwch + (long)i*EE*EE, pwcl + (long)i*EE*EE,
                      Wcb + (long)i*EE, px, py, R, EE, EE, 1, 0, 0, 0, 0);
        inorm_sf2<<<dim3(BB, 4), 512>>>(py);
        inorm_apply<<<(TOT/4 + 255)/256, 256>>>(py, n1g + (long)i*EE, n1b + (long)i*EE,
                                                px1, px1h, px1l);
        launch_hl_128(px1h, px1l, pf1h + (long)i*FFHH*EE, pf1l + (long)i*FFHH*EE,
                      fb1 + (long)i*FFHH, pffhh, pffhl, R, EE, FFHH, 1, 0, 0, 0, 1);
        launch_f32_64(pffhh, pffhl, pf2h + (long)i*EE*FFHH, pf2l + (long)i*EE*FFHH,
                      fb2 + (long)i*EE, px1, py, R, FFHH, EE, 1, 0, 0, 0, 0);
        inorm_sf2<<<dim3(BB, 4), 512>>>(py);
        inorm_apply<<<(TOT/4 + 255)/256, 256>>>(py, n2g + (long)i*EE, n2b + (long)i*EE,
                                                px, pxh, pxl);
    }

    // ---- decoder ----
    launch_f32_128(pxh, pxl, pwkvh, pwkvl, 0, 0, pkvd, R, EE, 256, 1, 0, 0, 0, 0);
    build_cat<<<BB*MM, EE>>>(loadv, cur, subn, subl, sel, n2b + (long)(NLL-1)*EE);
    launch_f32_64(pcatlh, pcatll, pwqlh, pwqll, 0, 0, pqloc, R, 256, EE, 1, 0, 0, 0, 0);
    launch_f32_64(pcatrh, pcatrl, pwpah, pwpal, 0, 0, pqrout, R, KRT, EE, 1, 0, 0, 0, 0);
    attn_mma<<<dim3(HH, BB), 256, ATTN2_SMEM>>>(
        pqloc, pqrout, pflag, 128, pkvd, 256, pkvd + 128, 256, mask, pattnh, pattnl);
    launch_hl_64(pattnh, pattnl, pwdch, pwdcl, dWcb, pscoreh, pscorel,
                 R, EE, EE, 1, 0, 0, 0, 0);
    launch_f32_128(pscoreh, pscorel, pxh, pxl, 0, 0, psn, MM, EE, NN, BB,
                   (long)MM*EE, (long)NN*EE, (long)MM*NN, 0);
    final_kernel<<<BB*MM, 256>>>(mask, out);
}